// round 6
// baseline (speedup 1.0000x reference)
#include <cuda_runtime.h>
#include <cstdint>

#define NPIX   6400
#define SCALE  0.17677669529663687f   // 32^-0.5

// Scratch (device globals)
__device__ float g_qkv [4 * NPIX * 768];   // [b][n][o] pixel-major, fp32
__device__ float g_attn[4 * 256 * 6400];   // [b][ch][n] channel-major, tf32 bits
__device__ float g_wqT [256 * 768];        // w_qkv^T: [c][o], tf32 bits
__device__ float g_wpT [256 * 256];        // w_proj^T: [c][o], tf32 bits

// ---------------------------------------------------------------------------
// Helpers (sm_80-class PTX: family-safe on compute_103)
// ---------------------------------------------------------------------------
__device__ __forceinline__ uint32_t smem_u32(const void* p) {
    uint32_t a;
    asm("{ .reg .u64 t; cvta.to.shared.u64 t, %1; cvt.u32.u64 %0, t; }" : "=r"(a) : "l"(p));
    return a;
}
__device__ __forceinline__ void cp16(uint32_t dst, const void* src) {
    asm volatile("cp.async.cg.shared.global [%0], [%1], 16;" :: "r"(dst), "l"(src));
}
#define CP_COMMIT() asm volatile("cp.async.commit_group;" ::: "memory")
#define CP_WAIT1()  asm volatile("cp.async.wait_group 1;" ::: "memory")

__device__ __forceinline__ uint32_t f2tf32(float x) {
    uint32_t u;
    asm("cvt.rna.tf32.f32 %0, %1;" : "=r"(u) : "f"(x));
    return u;
}
__device__ __forceinline__ void mma_tf32(float c[4],
                                         uint32_t a0, uint32_t a1, uint32_t a2, uint32_t a3,
                                         uint32_t b0, uint32_t b1) {
    asm volatile("mma.sync.aligned.m16n8k8.row.col.f32.tf32.tf32.f32 "
                 "{%0,%1,%2,%3}, {%4,%5,%6,%7}, {%8,%9}, {%0,%1,%2,%3};"
                 : "+f"(c[0]), "+f"(c[1]), "+f"(c[2]), "+f"(c[3])
                 : "r"(a0), "r"(a1), "r"(a2), "r"(a3), "r"(b0), "r"(b1));
}

// Smem: per stage two [16 k][136] tiles (A = data, B = weightsT)
#define TS      136
#define TSZ     (16 * TS)            // 2176 floats
#define STAGE_F (2 * TSZ)            // 4352 floats (17KB); x2 stages = 34KB

// ---------------------------------------------------------------------------
// Weight transpose + tf32 prologue: g_wT[c][o] = tf32(w[o][c])
// ---------------------------------------------------------------------------
__global__ __launch_bounds__(256) void conv_w(const float* __restrict__ wq,
                                              const float* __restrict__ wp)
{
    const int o = blockIdx.x;            // 0..1023: 0..767 wq, 768..1023 wp
    const int c = threadIdx.x;           // 0..255
    if (o < 768) {
        g_wqT[c * 768 + o] = __uint_as_float(f2tf32(wq[o * 256 + c]));
    } else {
        int r = o - 768;
        g_wpT[c * 256 + r] = __uint_as_float(f2tf32(wp[r * 256 + c]));
    }
}

// ---------------------------------------------------------------------------
// GEMM k-tile compute. M = pixels, N = out-channels, K = c.
// A tile As[k][pix] (stride TS), B tile Bs[k][o] (stride TS).
// CVT_A: convert A elements to tf32 at fragment load (raw fp32 source).
// ---------------------------------------------------------------------------
template <bool CVT_A>
__device__ __forceinline__ void gemm_ktile(const float* As, const float* Bs,
                                           int wm0, int wn0, int row, int colk,
                                           float acc[4][4][4]) {
    #pragma unroll
    for (int ks = 0; ks < 2; ks++) {
        const int kb = ks * 8;
        uint32_t a[4][4], bfr[4][2];
        #pragma unroll
        for (int mt = 0; mt < 4; mt++) {
            const int pix = wm0 + mt * 16 + row;
            const float* p0 = As + (kb + colk) * TS + pix;
            const float* p1 = As + (kb + colk + 4) * TS + pix;
            if (CVT_A) {
                a[mt][0] = f2tf32(p0[0]); a[mt][1] = f2tf32(p0[8]);
                a[mt][2] = f2tf32(p1[0]); a[mt][3] = f2tf32(p1[8]);
            } else {
                a[mt][0] = __float_as_uint(p0[0]); a[mt][1] = __float_as_uint(p0[8]);
                a[mt][2] = __float_as_uint(p1[0]); a[mt][3] = __float_as_uint(p1[8]);
            }
        }
        #pragma unroll
        for (int nt = 0; nt < 4; nt++) {
            const float* bb = Bs + (kb + colk) * TS + wn0 + nt * 8 + row;
            bfr[nt][0] = __float_as_uint(bb[0]);
            bfr[nt][1] = __float_as_uint(bb[4 * TS]);
        }
        #pragma unroll
        for (int mt = 0; mt < 4; mt++)
            #pragma unroll
            for (int nt = 0; nt < 4; nt++)
                mma_tf32(acc[mt][nt], a[mt][0], a[mt][1], a[mt][2], a[mt][3],
                         bfr[nt][0], bfr[nt][1]);
    }
}

// ---------------------------------------------------------------------------
// Kernel A: g_qkv[b][n][o] = sum_c y[b][c][n] * w_qkv[o][c]
// A = y tile (raw fp32, cvt at fragment), B = g_wqT tile.
// ---------------------------------------------------------------------------
__global__ __launch_bounds__(256, 2) void qkv_gemm(const float* __restrict__ rgb,
                                                   const float* __restrict__ ir)
{
    __shared__ __align__(16) float buf[2 * STAGE_F];

    const int b  = blockIdx.z;
    const int p0 = blockIdx.x * 128;   // pixel tile base (M)
    const int o0 = blockIdx.y * 128;   // out-channel tile base (N)
    const int tid = threadIdx.x;
    const int wid = tid >> 5, lane = tid & 31;
    const int wm0 = (wid >> 2) * 64, wn0 = (wid & 3) * 32;
    const int row = lane >> 2, colk = lane & 3;

    const float* rb = rgb + (size_t)b * 128 * NPIX;
    const float* ib = ir  + (size_t)b * 128 * NPIX;

    const int k_0 = tid >> 5,       nc0 = tid & 31;          // chunk 0: rows 0..7
    const int k_1 = (tid + 256) >> 5, nc1 = tid & 31;        // chunk 1: rows 8..15

    const uint32_t sbase = smem_u32(buf);

    auto load_tile = [&](int kt, int stage) {
        const int k0 = kt * 16;
        const uint32_t As = sbase + stage * STAGE_F * 4;
        const uint32_t Bs = As + TSZ * 4;
        int c0 = k0 + k_0, c1 = k0 + k_1;
        const float* s0 = (c0 < 128) ? (rb + (size_t)c0 * NPIX) : (ib + (size_t)(c0 - 128) * NPIX);
        const float* s1 = (c1 < 128) ? (rb + (size_t)c1 * NPIX) : (ib + (size_t)(c1 - 128) * NPIX);
        cp16(As + (k_0 * TS + nc0 * 4) * 4, s0 + p0 + nc0 * 4);
        cp16(As + (k_1 * TS + nc1 * 4) * 4, s1 + p0 + nc1 * 4);
        cp16(Bs + (k_0 * TS + nc0 * 4) * 4, g_wqT + (size_t)c0 * 768 + o0 + nc0 * 4);
        cp16(Bs + (k_1 * TS + nc1 * 4) * 4, g_wqT + (size_t)c1 * 768 + o0 + nc1 * 4);
    };

    float acc[4][4][4];
    #pragma unroll
    for (int mt = 0; mt < 4; mt++)
        #pragma unroll
        for (int nt = 0; nt < 4; nt++)
            #pragma unroll
            for (int i = 0; i < 4; i++) acc[mt][nt][i] = 0.f;

    load_tile(0, 0); CP_COMMIT();
    load_tile(1, 1); CP_COMMIT();

    for (int kt = 0; kt < 16; kt++) {
        CP_WAIT1();
        __syncthreads();
        const float* As = buf + (kt & 1) * STAGE_F;
        const float* Bs = As + TSZ;
        gemm_ktile<true>(As, Bs, wm0, wn0, row, colk, acc);
        __syncthreads();
        if (kt + 2 < 16) load_tile(kt + 2, kt & 1);
        CP_COMMIT();
    }

    // Epilogue: pixel-major writes, float2 contiguous in o
    float* outb = g_qkv + (size_t)b * NPIX * 768;
    #pragma unroll
    for (int mt = 0; mt < 4; mt++) {
        #pragma unroll
        for (int nt = 0; nt < 4; nt++) {
            int pix = p0 + wm0 + mt * 16 + row;
            int o = o0 + wn0 + nt * 8 + 2 * colk;
            *(float2*)(outb + (size_t)pix * 768 + o) =
                make_float2(acc[mt][nt][0], acc[mt][nt][1]);
            *(float2*)(outb + (size_t)(pix + 8) * 768 + o) =
                make_float2(acc[mt][nt][2], acc[mt][nt][3]);
        }
    }
}

// ---------------------------------------------------------------------------
// Kernel B: dilated local attention, pixel-major qkv, float4 loads.
// Writes g_attn channel-major, tf32-rounded (proj's A operand).
// ---------------------------------------------------------------------------
__global__ __launch_bounds__(256) void attn_kernel()
{
    const int n    = blockIdx.x * 256 + threadIdx.x;
    const int dh   = blockIdx.y;
    const int dil  = dh >> 2;
    const int head = dh & 3;
    const int b    = blockIdx.z;
    const int d    = dil ? 3 : 2;

    const int r = n / 80;
    const int c = n % 80;

    const float* base = g_qkv + ((size_t)(b * NPIX + n)) * 768 + dil * 128 + head * 32;
    const float* kb = base + 256;
    const float* vb = base + 512;

    float4 q[8];
    #pragma unroll
    for (int i = 0; i < 8; i++) q[i] = ((const float4*)base)[i];

    float sc[9];
    #pragma unroll
    for (int jj = 0; jj < 9; jj++) {
        int di = jj / 3 - 1, dj = jj % 3 - 1;
        int rr = r + di * d, cc = c + dj * d;
        float s = 0.f;
        if (rr >= 0 && rr < 80 && cc >= 0 && cc < 80) {
            const float* kp = kb + (size_t)(di * d * 80 + dj * d) * 768;
            #pragma unroll
            for (int i = 0; i < 8; i++) {
                float4 kv = ((const float4*)kp)[i];
                s = fmaf(q[i].x, kv.x, s); s = fmaf(q[i].y, kv.y, s);
                s = fmaf(q[i].z, kv.z, s); s = fmaf(q[i].w, kv.w, s);
            }
        }
        sc[jj] = s * SCALE;
    }

    float m = sc[0];
    #pragma unroll
    for (int jj = 1; jj < 9; jj++) m = fmaxf(m, sc[jj]);
    float sum = 0.f;
    #pragma unroll
    for (int jj = 0; jj < 9; jj++) { sc[jj] = __expf(sc[jj] - m); sum += sc[jj]; }
    const float inv = 1.f / sum;

    float4 out[8];
    #pragma unroll
    for (int i = 0; i < 8; i++) out[i] = make_float4(0.f, 0.f, 0.f, 0.f);

    #pragma unroll
    for (int jj = 0; jj < 9; jj++) {
        int di = jj / 3 - 1, dj = jj % 3 - 1;
        int rr = r + di * d, cc = c + dj * d;
        if (rr >= 0 && rr < 80 && cc >= 0 && cc < 80) {
            const float* vp = vb + (size_t)(di * d * 80 + dj * d) * 768;
            float p = sc[jj] * inv;
            #pragma unroll
            for (int i = 0; i < 8; i++) {
                float4 vv = ((const float4*)vp)[i];
                out[i].x = fmaf(p, vv.x, out[i].x);
                out[i].y = fmaf(p, vv.y, out[i].y);
                out[i].z = fmaf(p, vv.z, out[i].z);
                out[i].w = fmaf(p, vv.w, out[i].w);
            }
        }
    }

    // channel-major tf32 write (A-tile layout for proj)
    float* ob = g_attn + ((size_t)(b * 256 + dil * 128 + head * 32)) * NPIX + n;
    #pragma unroll
    for (int i = 0; i < 8; i++) {
        ob[(4 * i + 0) * NPIX] = __uint_as_float(f2tf32(out[i].x));
        ob[(4 * i + 1) * NPIX] = __uint_as_float(f2tf32(out[i].y));
        ob[(4 * i + 2) * NPIX] = __uint_as_float(f2tf32(out[i].z));
        ob[(4 * i + 3) * NPIX] = __uint_as_float(f2tf32(out[i].w));
    }
}

// ---------------------------------------------------------------------------
// Kernel C: out[b][n][o] = sum_c attn[b][c][n]*w_proj[o][c] + bias[o] + resid
// A = g_attn tile (tf32 bits), B = g_wpT tile. Direct final-layout output.
// ---------------------------------------------------------------------------
__global__ __launch_bounds__(256, 2) void proj_kernel(const float* __restrict__ bias,
                                                      const float* __restrict__ rgb,
                                                      const float* __restrict__ ir,
                                                      float* __restrict__ out)
{
    __shared__ __align__(16) float buf[2 * STAGE_F];

    const int b  = blockIdx.z;
    const int p0 = blockIdx.x * 128;
    const int o0 = blockIdx.y * 128;
    const int tid = threadIdx.x;
    const int wid = tid >> 5, lane = tid & 31;
    const int wm0 = (wid >> 2) * 64, wn0 = (wid & 3) * 32;
    const int row = lane >> 2, colk = lane & 3;

    const float* ab = g_attn + (size_t)b * 256 * NPIX;

    const int k_0 = tid >> 5,         nc0 = tid & 31;
    const int k_1 = (tid + 256) >> 5, nc1 = tid & 31;

    const uint32_t sbase = smem_u32(buf);

    auto load_tile = [&](int kt, int stage) {
        const int k0 = kt * 16;
        const uint32_t As = sbase + stage * STAGE_F * 4;
        const uint32_t Bs = As + TSZ * 4;
        cp16(As + (k_0 * TS + nc0 * 4) * 4, ab + (size_t)(k0 + k_0) * NPIX + p0 + nc0 * 4);
        cp16(As + (k_1 * TS + nc1 * 4) * 4, ab + (size_t)(k0 + k_1) * NPIX + p0 + nc1 * 4);
        cp16(Bs + (k_0 * TS + nc0 * 4) * 4, g_wpT + (size_t)(k0 + k_0) * 256 + o0 + nc0 * 4);
        cp16(Bs + (k_1 * TS + nc1 * 4) * 4, g_wpT + (size_t)(k0 + k_1) * 256 + o0 + nc1 * 4);
    };

    float acc[4][4][4];
    #pragma unroll
    for (int mt = 0; mt < 4; mt++)
        #pragma unroll
        for (int nt = 0; nt < 4; nt++)
            #pragma unroll
            for (int i = 0; i < 4; i++) acc[mt][nt][i] = 0.f;

    load_tile(0, 0); CP_COMMIT();
    load_tile(1, 1); CP_COMMIT();

    for (int kt = 0; kt < 16; kt++) {
        CP_WAIT1();
        __syncthreads();
        const float* As = buf + (kt & 1) * STAGE_F;
        const float* Bs = As + TSZ;
        gemm_ktile<false>(As, Bs, wm0, wn0, row, colk, acc);
        __syncthreads();
        if (kt + 2 < 16) load_tile(kt + 2, kt & 1);
        CP_COMMIT();
    }

    // Epilogue: bias + residual, final layout [b][n][256]
    const float* resb = ((o0 == 0) ? rgb : ir) + (size_t)b * 128 * NPIX;
    float* outb = out + (size_t)b * NPIX * 256;

    #pragma unroll
    for (int mt = 0; mt < 4; mt++) {
        #pragma unroll
        for (int nt = 0; nt < 4; nt++) {
            int pix = p0 + wm0 + mt * 16 + row;
            int o = o0 + wn0 + nt * 8 + 2 * colk;
            float b0 = __ldg(bias + o), b1 = __ldg(bias + o + 1);
            const float* r0p = resb + (size_t)(o & 127) * NPIX;
            const float* r1p = resb + (size_t)((o + 1) & 127) * NPIX;
            *(float2*)(outb + (size_t)pix * 256 + o) = make_float2(
                acc[mt][nt][0] + b0 + r0p[pix], acc[mt][nt][1] + b1 + r1p[pix]);
            *(float2*)(outb + (size_t)(pix + 8) * 256 + o) = make_float2(
                acc[mt][nt][2] + b0 + r0p[pix + 8], acc[mt][nt][3] + b1 + r1p[pix + 8]);
        }
    }
}

// ---------------------------------------------------------------------------
extern "C" void kernel_launch(void* const* d_in, const int* in_sizes, int n_in,
                              void* d_out, int out_size)
{
    const float* rgb    = (const float*)d_in[0];
    const float* ir     = (const float*)d_in[1];
    const float* w_qkv  = (const float*)d_in[2];
    const float* w_proj = (const float*)d_in[3];
    const float* b_proj = (const float*)d_in[4];
    float* out = (float*)d_out;

    conv_w<<<1024, 256>>>(w_qkv, w_proj);
    qkv_gemm<<<dim3(50, 6, 4), 256>>>(rgb, ir);
    attn_kernel<<<dim3(25, 8, 4), 256>>>();
    proj_kernel<<<dim3(50, 2, 4), 256>>>(b_proj, rgb, ir, out);
}

// round 7
// speedup vs baseline: 1.4674x; 1.4674x over previous
#include <cuda_runtime.h>
#include <cstdint>

#define NPIX   6400
#define SCALE  0.17677669529663687f   // 32^-0.5

// Scratch (device globals), channel-major layouts
__device__ float g_qkv [4 * 768 * 6400];   // [b][o][n]  fp32 (MMA output)
__device__ float g_attn[4 * 256 * 6400];   // [b][ch][n] tf32-rounded bits
__device__ float g_wq  [768 * 256];        // w_qkv, tf32-rounded, k-interleaved
__device__ float g_wp  [256 * 256];        // w_proj, tf32-rounded, k-interleaved

// ---------------------------------------------------------------------------
// Helpers (sm_80-class PTX only: family-safe on compute_103)
// ---------------------------------------------------------------------------
__device__ __forceinline__ uint32_t smem_u32(const void* p) {
    uint32_t a;
    asm("{ .reg .u64 t; cvta.to.shared.u64 t, %1; cvt.u32.u64 %0, t; }" : "=r"(a) : "l"(p));
    return a;
}
__device__ __forceinline__ void cp16(uint32_t dst, const void* src) {
    asm volatile("cp.async.cg.shared.global [%0], [%1], 16;" :: "r"(dst), "l"(src));
}
#define CP_COMMIT() asm volatile("cp.async.commit_group;" ::: "memory")
#define CP_WAIT1()  asm volatile("cp.async.wait_group 1;" ::: "memory")

__device__ __forceinline__ uint32_t f2tf32(float x) {
    uint32_t u;
    asm("cvt.rna.tf32.f32 %0, %1;" : "=r"(u) : "f"(x));
    return u;
}
__device__ __forceinline__ void mma_tf32(float c[4],
                                         uint32_t a0, uint32_t a1, uint32_t a2, uint32_t a3,
                                         uint32_t b0, uint32_t b1) {
    asm volatile("mma.sync.aligned.m16n8k8.row.col.f32.tf32.tf32.f32 "
                 "{%0,%1,%2,%3}, {%4,%5,%6,%7}, {%8,%9}, {%0,%1,%2,%3};"
                 : "+f"(c[0]), "+f"(c[1]), "+f"(c[2]), "+f"(c[3])
                 : "r"(a0), "r"(a1), "r"(a2), "r"(a3), "r"(b0), "r"(b1));
}

// Smem layout (per stage): A [128 m][24] floats (16 k interleaved + pad),
//                          B [16 k][136] floats
#define AS_STRIDE 24
#define AS_SIZE   (128 * AS_STRIDE)      // 3072 floats
#define BS_STRIDE 136
#define BS_SIZE   (16 * BS_STRIDE)       // 2176 floats
#define STAGE_F   (AS_SIZE + BS_SIZE)    // 5248 floats (20.5KB) x2 = 41KB

// ---------------------------------------------------------------------------
// Weight prologue: tf32-rounded + k-interleaved within each 8-block:
// dst[o][ (k & ~7) | (((k&3)<<1)|(k>>2&1)) ] = tf32(src[o][k])
// ---------------------------------------------------------------------------
__global__ __launch_bounds__(256) void conv_w(const float* __restrict__ wq,
                                              const float* __restrict__ wp)
{
    const int row = blockIdx.x;          // 0..1023 : 0..767 wq, 768..1023 wp
    const int k   = threadIdx.x;         // 0..255
    const int kp  = (k & ~7) | (((k & 3) << 1) | ((k >> 2) & 1));
    if (row < 768) {
        g_wq[row * 256 + kp] = __uint_as_float(f2tf32(wq[row * 256 + k]));
    } else {
        int r = row - 768;
        g_wp[r * 256 + kp] = __uint_as_float(f2tf32(wp[r * 256 + k]));
    }
}

// ---------------------------------------------------------------------------
// GEMM k-tile compute: warp grid 2(m) x 4(n), warp tile 64 x 32.
// A fragments: raw tf32 bits (pre-converted weights, k-interleaved pairs).
// B fragments: CVT_B ? cvt at load (raw fp32 y) : raw bits (g_attn).
// ---------------------------------------------------------------------------
template <bool CVT_B>
__device__ __forceinline__ void gemm_ktile(const float* As, const float* Bs,
                                           int wm0, int wn0, int row, int colk,
                                           float acc[4][4][4]) {
    #pragma unroll
    for (int ks = 0; ks < 2; ks++) {
        const int kb = ks * 8;
        uint32_t a[4][4], bfr[4][2];
        #pragma unroll
        for (int mt = 0; mt < 4; mt++) {
            const float* ab = As + (wm0 + mt * 16 + row) * AS_STRIDE + kb + 2 * colk;
            float2 lo = *(const float2*)ab;                    // k=colk, k=colk+4
            float2 hi = *(const float2*)(ab + 8 * AS_STRIDE);  // row+8
            a[mt][0] = __float_as_uint(lo.x);
            a[mt][1] = __float_as_uint(hi.x);
            a[mt][2] = __float_as_uint(lo.y);
            a[mt][3] = __float_as_uint(hi.y);
        }
        #pragma unroll
        for (int nt = 0; nt < 4; nt++) {
            const float* bb = Bs + (kb + colk) * BS_STRIDE + wn0 + nt * 8 + row;
            if (CVT_B) {
                bfr[nt][0] = f2tf32(bb[0]);
                bfr[nt][1] = f2tf32(bb[4 * BS_STRIDE]);
            } else {
                bfr[nt][0] = __float_as_uint(bb[0]);
                bfr[nt][1] = __float_as_uint(bb[4 * BS_STRIDE]);
            }
        }
        #pragma unroll
        for (int mt = 0; mt < 4; mt++)
            #pragma unroll
            for (int nt = 0; nt < 4; nt++)
                mma_tf32(acc[mt][nt], a[mt][0], a[mt][1], a[mt][2], a[mt][3],
                         bfr[nt][0], bfr[nt][1]);
    }
}

// ---------------------------------------------------------------------------
// Kernel A: qkv[b][o][n] = sum_c w_qkv[o][c] * y[b][c][n]
// A = g_wq (tf32, interleaved), B = y direct from rgb/ir (cvt at fragment).
// ---------------------------------------------------------------------------
__global__ __launch_bounds__(256, 2) void qkv_gemm(const float* __restrict__ rgb,
                                                   const float* __restrict__ ir)
{
    __shared__ __align__(16) float buf[2 * STAGE_F];

    const int b  = blockIdx.z;
    const int n0 = blockIdx.x * 128;
    const int m0 = blockIdx.y * 128;
    const int tid = threadIdx.x;
    const int wid = tid >> 5, lane = tid & 31;
    const int wm0 = (wid >> 2) * 64, wn0 = (wid & 3) * 32;
    const int row = lane >> 2, colk = lane & 3;

    const float* rb = rgb + (size_t)b * 128 * NPIX;
    const float* ib = ir  + (size_t)b * 128 * NPIX;

    const int am0 = (tid) >> 2,        akc0 = (tid) & 3;
    const int am1 = (tid + 256) >> 2,  akc1 = (tid + 256) & 3;
    const int bk0 = (tid) >> 5,        bnc0 = (tid) & 31;
    const int bk1 = (tid + 256) >> 5,  bnc1 = (tid + 256) & 31;

    const uint32_t sbase = smem_u32(buf);

    auto load_tile = [&](int kt, int stage) {
        const int k0 = kt * 16;
        const uint32_t As = sbase + stage * STAGE_F * 4;
        const uint32_t Bs = As + AS_SIZE * 4;
        cp16(As + (am0 * AS_STRIDE + akc0 * 4) * 4, g_wq + (size_t)(m0 + am0) * 256 + k0 + akc0 * 4);
        cp16(As + (am1 * AS_STRIDE + akc1 * 4) * 4, g_wq + (size_t)(m0 + am1) * 256 + k0 + akc1 * 4);
        int c0 = k0 + bk0, c1 = k0 + bk1;
        const float* s0 = (c0 < 128) ? (rb + (size_t)c0 * NPIX) : (ib + (size_t)(c0 - 128) * NPIX);
        const float* s1 = (c1 < 128) ? (rb + (size_t)c1 * NPIX) : (ib + (size_t)(c1 - 128) * NPIX);
        cp16(Bs + (bk0 * BS_STRIDE + bnc0 * 4) * 4, s0 + n0 + bnc0 * 4);
        cp16(Bs + (bk1 * BS_STRIDE + bnc1 * 4) * 4, s1 + n0 + bnc1 * 4);
    };

    float acc[4][4][4];
    #pragma unroll
    for (int mt = 0; mt < 4; mt++)
        #pragma unroll
        for (int nt = 0; nt < 4; nt++)
            #pragma unroll
            for (int i = 0; i < 4; i++) acc[mt][nt][i] = 0.f;

    load_tile(0, 0); CP_COMMIT();
    load_tile(1, 1); CP_COMMIT();

    for (int kt = 0; kt < 16; kt++) {
        CP_WAIT1();
        __syncthreads();
        const float* As = buf + (kt & 1) * STAGE_F;
        const float* Bs = As + AS_SIZE;
        gemm_ktile<true>(As, Bs, wm0, wn0, row, colk, acc);
        __syncthreads();
        if (kt + 2 < 16) load_tile(kt + 2, kt & 1);
        CP_COMMIT();
    }

    float* outb = g_qkv + (size_t)b * 768 * NPIX;
    #pragma unroll
    for (int mt = 0; mt < 4; mt++) {
        #pragma unroll
        for (int nt = 0; nt < 4; nt++) {
            int o = m0 + wm0 + mt * 16 + row;
            int n = n0 + wn0 + nt * 8 + 2 * colk;
            *(float2*)(outb + (size_t)o * NPIX + n) =
                make_float2(acc[mt][nt][0], acc[mt][nt][1]);
            *(float2*)(outb + (size_t)(o + 8) * NPIX + n) =
                make_float2(acc[mt][nt][2], acc[mt][nt][3]);
        }
    }
}

// ---------------------------------------------------------------------------
// Kernel B: dilated local attention (channel-major), 1 thread per (b,dil,head,pix)
// Output written tf32-rounded (proj consumes raw bits).
// ---------------------------------------------------------------------------
__global__ __launch_bounds__(256) void attn_kernel()
{
    const int n    = blockIdx.x * 256 + threadIdx.x;
    const int dh   = blockIdx.y;
    const int dil  = dh >> 2;
    const int head = dh & 3;
    const int b    = blockIdx.z;
    const int d    = dil ? 3 : 2;

    const int r = n / 80;
    const int c = n % 80;

    const float* qb = g_qkv + ((size_t)(b * 768 + dil * 128 + head * 32)) * NPIX + n;
    const float* kb = qb + (size_t)256 * NPIX;
    const float* vb = qb + (size_t)512 * NPIX;

    float q[32];
    #pragma unroll
    for (int hd = 0; hd < 32; hd++) q[hd] = qb[hd * NPIX];

    float sc[9];
    #pragma unroll
    for (int jj = 0; jj < 9; jj++) {
        int di = jj / 3 - 1, dj = jj % 3 - 1;
        int rr = r + di * d, cc = c + dj * d;
        float s = 0.f;
        if (rr >= 0 && rr < 80 && cc >= 0 && cc < 80) {
            int off = di * d * 80 + dj * d;
            #pragma unroll
            for (int hd = 0; hd < 32; hd++)
                s = fmaf(q[hd], kb[hd * NPIX + off], s);
        }
        sc[jj] = s * SCALE;
    }

    float m = sc[0];
    #pragma unroll
    for (int jj = 1; jj < 9; jj++) m = fmaxf(m, sc[jj]);
    float sum = 0.f;
    #pragma unroll
    for (int jj = 0; jj < 9; jj++) { sc[jj] = __expf(sc[jj] - m); sum += sc[jj]; }
    const float inv = 1.f / sum;

    float out[32];
    #pragma unroll
    for (int hd = 0; hd < 32; hd++) out[hd] = 0.f;

    #pragma unroll
    for (int jj = 0; jj < 9; jj++) {
        int di = jj / 3 - 1, dj = jj % 3 - 1;
        int rr = r + di * d, cc = c + dj * d;
        if (rr >= 0 && rr < 80 && cc >= 0 && cc < 80) {
            int off = di * d * 80 + dj * d;
            float p = sc[jj] * inv;
            #pragma unroll
            for (int hd = 0; hd < 32; hd++)
                out[hd] = fmaf(p, vb[hd * NPIX + off], out[hd]);
        }
    }

    float* ob = g_attn + ((size_t)(b * 256 + dil * 128 + head * 32)) * NPIX + n;
    #pragma unroll
    for (int hd = 0; hd < 32; hd++)
        ob[hd * NPIX] = __uint_as_float(f2tf32(out[hd]));
}

// ---------------------------------------------------------------------------
// Kernel C: out[b][n][o] = sum_c w_proj[o][c]*attn[b][c][n] + b_proj[o] + resid
// ---------------------------------------------------------------------------
__global__ __launch_bounds__(256, 2) void proj_kernel(const float* __restrict__ bias,
                                                      const float* __restrict__ rgb,
                                                      const float* __restrict__ ir,
                                                      float* __restrict__ out)
{
    __shared__ __align__(16) float buf[2 * STAGE_F];

    const int b  = blockIdx.z;
    const int n0 = blockIdx.x * 128;
    const int m0 = blockIdx.y * 128;
    const int tid = threadIdx.x;
    const int wid = tid >> 5, lane = tid & 31;
    const int wm0 = (wid >> 2) * 64, wn0 = (wid & 3) * 32;
    const int row = lane >> 2, colk = lane & 3;

    const float* ab = g_attn + (size_t)b * 256 * NPIX;

    const int am0 = (tid) >> 2,        akc0 = (tid) & 3;
    const int am1 = (tid + 256) >> 2,  akc1 = (tid + 256) & 3;
    const int bk0 = (tid) >> 5,        bnc0 = (tid) & 31;
    const int bk1 = (tid + 256) >> 5,  bnc1 = (tid + 256) & 31;

    const uint32_t sbase = smem_u32(buf);

    auto load_tile = [&](int kt, int stage) {
        const int k0 = kt * 16;
        const uint32_t As = sbase + stage * STAGE_F * 4;
        const uint32_t Bs = As + AS_SIZE * 4;
        cp16(As + (am0 * AS_STRIDE + akc0 * 4) * 4, g_wp + (size_t)(m0 + am0) * 256 + k0 + akc0 * 4);
        cp16(As + (am1 * AS_STRIDE + akc1 * 4) * 4, g_wp + (size_t)(m0 + am1) * 256 + k0 + akc1 * 4);
        cp16(Bs + (bk0 * BS_STRIDE + bnc0 * 4) * 4, ab + (size_t)(k0 + bk0) * NPIX + n0 + bnc0 * 4);
        cp16(Bs + (bk1 * BS_STRIDE + bnc1 * 4) * 4, ab + (size_t)(k0 + bk1) * NPIX + n0 + bnc1 * 4);
    };

    float acc[4][4][4];
    #pragma unroll
    for (int mt = 0; mt < 4; mt++)
        #pragma unroll
        for (int nt = 0; nt < 4; nt++)
            #pragma unroll
            for (int i = 0; i < 4; i++) acc[mt][nt][i] = 0.f;

    load_tile(0, 0); CP_COMMIT();
    load_tile(1, 1); CP_COMMIT();

    for (int kt = 0; kt < 16; kt++) {
        CP_WAIT1();
        __syncthreads();
        const float* As = buf + (kt & 1) * STAGE_F;
        const float* Bs = As + AS_SIZE;
        gemm_ktile<false>(As, Bs, wm0, wn0, row, colk, acc);
        __syncthreads();
        if (kt + 2 < 16) load_tile(kt + 2, kt & 1);
        CP_COMMIT();
    }

    // Epilogue: + bias + residual, write out[b][n][o] (o contiguous)
    const float* resb = ((m0 == 0) ? rgb : ir) + (size_t)b * 128 * NPIX;
    float* outb = out + (size_t)b * NPIX * 256;

    #pragma unroll
    for (int mt = 0; mt < 4; mt++) {
        const int o_lo = m0 + wm0 + mt * 16 + row;
        const int o_hi = o_lo + 8;
        const float bias_lo = __ldg(bias + o_lo);
        const float bias_hi = __ldg(bias + o_hi);
        const float* res_lo = resb + (size_t)(o_lo & 127) * NPIX;
        const float* res_hi = resb + (size_t)(o_hi & 127) * NPIX;
        #pragma unroll
        for (int nt = 0; nt < 4; nt++) {
            const int n = n0 + wn0 + nt * 8 + 2 * colk;
            outb[(size_t)n * 256 + o_lo]       = acc[mt][nt][0] + bias_lo + res_lo[n];
            outb[(size_t)(n + 1) * 256 + o_lo] = acc[mt][nt][1] + bias_lo + res_lo[n + 1];
            outb[(size_t)n * 256 + o_hi]       = acc[mt][nt][2] + bias_hi + res_hi[n];
            outb[(size_t)(n + 1) * 256 + o_hi] = acc[mt][nt][3] + bias_hi + res_hi[n + 1];
        }
    }
}

// ---------------------------------------------------------------------------
extern "C" void kernel_launch(void* const* d_in, const int* in_sizes, int n_in,
                              void* d_out, int out_size)
{
    const float* rgb    = (const float*)d_in[0];
    const float* ir     = (const float*)d_in[1];
    const float* w_qkv  = (const float*)d_in[2];
    const float* w_proj = (const float*)d_in[3];
    const float* b_proj = (const float*)d_in[4];
    float* out = (float*)d_out;

    conv_w<<<1024, 256>>>(w_qkv, w_proj);
    qkv_gemm<<<dim3(50, 6, 4), 256>>>(rgb, ir);
    attn_kernel<<<dim3(25, 8, 4), 256>>>();
    proj_kernel<<<dim3(50, 2, 4), 256>>>(b_proj, rgb, ir, out);
}

// round 8
// speedup vs baseline: 1.4887x; 1.0145x over previous
#include <cuda_runtime.h>
#include <cstdint>

#define NPIX   6400
#define SCALE  0.17677669529663687f   // 32^-0.5

// Scratch (device globals), channel-major layouts
__device__ float g_qkv [4 * 768 * 6400];   // [b][o][n]  fp32 (MMA output)
__device__ float g_attn[4 * 256 * 6400];   // [b][ch][n] tf32-rounded bits
__device__ float g_wq  [768 * 256];        // w_qkv, tf32-rounded, k-interleaved
__device__ float g_wp  [256 * 256];        // w_proj, tf32-rounded, k-interleaved

// ---------------------------------------------------------------------------
// Helpers (sm_80-class PTX only: family-safe on compute_103)
// ---------------------------------------------------------------------------
__device__ __forceinline__ uint32_t smem_u32(const void* p) {
    uint32_t a;
    asm("{ .reg .u64 t; cvta.to.shared.u64 t, %1; cvt.u32.u64 %0, t; }" : "=r"(a) : "l"(p));
    return a;
}
__device__ __forceinline__ void cp16(uint32_t dst, const void* src) {
    asm volatile("cp.async.cg.shared.global [%0], [%1], 16;" :: "r"(dst), "l"(src));
}
#define CP_COMMIT() asm volatile("cp.async.commit_group;" ::: "memory")
#define CP_WAIT1()  asm volatile("cp.async.wait_group 1;" ::: "memory")

__device__ __forceinline__ uint32_t f2tf32(float x) {
    uint32_t u;
    asm("cvt.rna.tf32.f32 %0, %1;" : "=r"(u) : "f"(x));
    return u;
}
__device__ __forceinline__ void mma_tf32(float c[4],
                                         uint32_t a0, uint32_t a1, uint32_t a2, uint32_t a3,
                                         uint32_t b0, uint32_t b1) {
    asm volatile("mma.sync.aligned.m16n8k8.row.col.f32.tf32.tf32.f32 "
                 "{%0,%1,%2,%3}, {%4,%5,%6,%7}, {%8,%9}, {%0,%1,%2,%3};"
                 : "+f"(c[0]), "+f"(c[1]), "+f"(c[2]), "+f"(c[3])
                 : "r"(a0), "r"(a1), "r"(a2), "r"(a3), "r"(b0), "r"(b1));
}

// Smem layout (per stage): A [128 m][24] floats (16 k interleaved + pad),
//                          B [16 k][136] floats
#define AS_STRIDE 24
#define AS_SIZE   (128 * AS_STRIDE)      // 3072 floats
#define BS_STRIDE 136
#define BS_SIZE   (16 * BS_STRIDE)       // 2176 floats
#define STAGE_F   (AS_SIZE + BS_SIZE)    // 5248 floats (20.5KB) x2 = 41KB

// ---------------------------------------------------------------------------
// Weight prologue: tf32-rounded + k-interleaved within each 8-block:
// dst[o][ (k & ~7) | (((k&3)<<1)|(k>>2&1)) ] = tf32(src[o][k])
// ---------------------------------------------------------------------------
__global__ __launch_bounds__(256) void conv_w(const float* __restrict__ wq,
                                              const float* __restrict__ wp)
{
    const int row = blockIdx.x;          // 0..1023 : 0..767 wq, 768..1023 wp
    const int k   = threadIdx.x;         // 0..255
    const int kp  = (k & ~7) | (((k & 3) << 1) | ((k >> 2) & 1));
    if (row < 768) {
        g_wq[row * 256 + kp] = __uint_as_float(f2tf32(wq[row * 256 + k]));
    } else {
        int r = row - 768;
        g_wp[r * 256 + kp] = __uint_as_float(f2tf32(wp[r * 256 + k]));
    }
}

// ---------------------------------------------------------------------------
// GEMM k-tile compute: warp grid 2(m) x 4(n), warp tile 64 x 32.
// A fragments: raw tf32 bits (pre-converted weights, k-interleaved pairs).
// B fragments: CVT_B ? cvt at load (raw fp32 y) : raw bits (g_attn).
// ---------------------------------------------------------------------------
template <bool CVT_B>
__device__ __forceinline__ void gemm_ktile(const float* As, const float* Bs,
                                           int wm0, int wn0, int row, int colk,
                                           float acc[4][4][4]) {
    #pragma unroll
    for (int ks = 0; ks < 2; ks++) {
        const int kb = ks * 8;
        uint32_t a[4][4], bfr[4][2];
        #pragma unroll
        for (int mt = 0; mt < 4; mt++) {
            const float* ab = As + (wm0 + mt * 16 + row) * AS_STRIDE + kb + 2 * colk;
            float2 lo = *(const float2*)ab;                    // k=colk, k=colk+4
            float2 hi = *(const float2*)(ab + 8 * AS_STRIDE);  // row+8
            a[mt][0] = __float_as_uint(lo.x);
            a[mt][1] = __float_as_uint(hi.x);
            a[mt][2] = __float_as_uint(lo.y);
            a[mt][3] = __float_as_uint(hi.y);
        }
        #pragma unroll
        for (int nt = 0; nt < 4; nt++) {
            const float* bb = Bs + (kb + colk) * BS_STRIDE + wn0 + nt * 8 + row;
            if (CVT_B) {
                bfr[nt][0] = f2tf32(bb[0]);
                bfr[nt][1] = f2tf32(bb[4 * BS_STRIDE]);
            } else {
                bfr[nt][0] = __float_as_uint(bb[0]);
                bfr[nt][1] = __float_as_uint(bb[4 * BS_STRIDE]);
            }
        }
        #pragma unroll
        for (int mt = 0; mt < 4; mt++)
            #pragma unroll
            for (int nt = 0; nt < 4; nt++)
                mma_tf32(acc[mt][nt], a[mt][0], a[mt][1], a[mt][2], a[mt][3],
                         bfr[nt][0], bfr[nt][1]);
    }
}

// ---------------------------------------------------------------------------
// Kernel A: qkv[b][o][n] = sum_c w_qkv[o][c] * y[b][c][n]
// A = g_wq (tf32, interleaved), B = y direct from rgb/ir (cvt at fragment).
// ---------------------------------------------------------------------------
__global__ __launch_bounds__(256, 2) void qkv_gemm(const float* __restrict__ rgb,
                                                   const float* __restrict__ ir)
{
    __shared__ __align__(16) float buf[2 * STAGE_F];

    const int b  = blockIdx.z;
    const int n0 = blockIdx.x * 128;
    const int m0 = blockIdx.y * 128;
    const int tid = threadIdx.x;
    const int wid = tid >> 5, lane = tid & 31;
    const int wm0 = (wid >> 2) * 64, wn0 = (wid & 3) * 32;
    const int row = lane >> 2, colk = lane & 3;

    const float* rb = rgb + (size_t)b * 128 * NPIX;
    const float* ib = ir  + (size_t)b * 128 * NPIX;

    const int am0 = (tid) >> 2,        akc0 = (tid) & 3;
    const int am1 = (tid + 256) >> 2,  akc1 = (tid + 256) & 3;
    const int bk0 = (tid) >> 5,        bnc0 = (tid) & 31;
    const int bk1 = (tid + 256) >> 5,  bnc1 = (tid + 256) & 31;

    const uint32_t sbase = smem_u32(buf);

    auto load_tile = [&](int kt, int stage) {
        const int k0 = kt * 16;
        const uint32_t As = sbase + stage * STAGE_F * 4;
        const uint32_t Bs = As + AS_SIZE * 4;
        cp16(As + (am0 * AS_STRIDE + akc0 * 4) * 4, g_wq + (size_t)(m0 + am0) * 256 + k0 + akc0 * 4);
        cp16(As + (am1 * AS_STRIDE + akc1 * 4) * 4, g_wq + (size_t)(m0 + am1) * 256 + k0 + akc1 * 4);
        int c0 = k0 + bk0, c1 = k0 + bk1;
        const float* s0 = (c0 < 128) ? (rb + (size_t)c0 * NPIX) : (ib + (size_t)(c0 - 128) * NPIX);
        const float* s1 = (c1 < 128) ? (rb + (size_t)c1 * NPIX) : (ib + (size_t)(c1 - 128) * NPIX);
        cp16(Bs + (bk0 * BS_STRIDE + bnc0 * 4) * 4, s0 + n0 + bnc0 * 4);
        cp16(Bs + (bk1 * BS_STRIDE + bnc1 * 4) * 4, s1 + n0 + bnc1 * 4);
    };

    float acc[4][4][4];
    #pragma unroll
    for (int mt = 0; mt < 4; mt++)
        #pragma unroll
        for (int nt = 0; nt < 4; nt++)
            #pragma unroll
            for (int i = 0; i < 4; i++) acc[mt][nt][i] = 0.f;

    load_tile(0, 0); CP_COMMIT();
    load_tile(1, 1); CP_COMMIT();

    for (int kt = 0; kt < 16; kt++) {
        CP_WAIT1();
        __syncthreads();
        const float* As = buf + (kt & 1) * STAGE_F;
        const float* Bs = As + AS_SIZE;
        gemm_ktile<true>(As, Bs, wm0, wn0, row, colk, acc);
        __syncthreads();
        if (kt + 2 < 16) load_tile(kt + 2, kt & 1);
        CP_COMMIT();
    }

    float* outb = g_qkv + (size_t)b * 768 * NPIX;
    #pragma unroll
    for (int mt = 0; mt < 4; mt++) {
        #pragma unroll
        for (int nt = 0; nt < 4; nt++) {
            int o = m0 + wm0 + mt * 16 + row;
            int n = n0 + wn0 + nt * 8 + 2 * colk;
            *(float2*)(outb + (size_t)o * NPIX + n) =
                make_float2(acc[mt][nt][0], acc[mt][nt][1]);
            *(float2*)(outb + (size_t)(o + 8) * NPIX + n) =
                make_float2(acc[mt][nt][2], acc[mt][nt][3]);
        }
    }
}

// ---------------------------------------------------------------------------
// Kernel B: dilated local attention, 2 lanes per (pixel, dil, head) unit.
// lane = pix(4b) | half<<4 : halves of hd split across lane pairs (xor 16);
// score reduced with one shfl_xor. OOB neighbors -> exact logit 0.
// ---------------------------------------------------------------------------
__global__ __launch_bounds__(256) void attn_kernel()
{
    const int tid  = threadIdx.x;
    const int wid  = tid >> 5, lane = tid & 31;
    const int half = lane >> 4;                    // hd half: 0 or 1
    const int n    = blockIdx.x * 128 + wid * 16 + (lane & 15);
    const int dh   = blockIdx.y;
    const int dil  = dh >> 2;
    const int head = dh & 3;
    const int b    = blockIdx.z;
    const int d    = dil ? 3 : 2;

    const int r = n / 80;
    const int c = n % 80;
    const int hd0 = half * 16;

    const float* qb = g_qkv + ((size_t)(b * 768 + dil * 128 + head * 32 + hd0)) * NPIX + n;
    const float* kb = qb + (size_t)256 * NPIX;
    const float* vb = qb + (size_t)512 * NPIX;

    float q[16];
    #pragma unroll
    for (int hd = 0; hd < 16; hd++) q[hd] = qb[hd * NPIX];

    float sc[9];
    #pragma unroll
    for (int jj = 0; jj < 9; jj++) {
        int di = jj / 3 - 1, dj = jj % 3 - 1;
        int rr = r + di * d, cc = c + dj * d;
        float s = 0.f;
        if (rr >= 0 && rr < 80 && cc >= 0 && cc < 80) {
            int off = di * d * 80 + dj * d;
            #pragma unroll
            for (int hd = 0; hd < 16; hd++)
                s = fmaf(q[hd], kb[hd * NPIX + off], s);
        }
        // combine the two hd-halves (lane pair xor 16)
        s += __shfl_xor_sync(0xFFFFFFFFu, s, 16);
        sc[jj] = s * SCALE;
    }

    float m = sc[0];
    #pragma unroll
    for (int jj = 1; jj < 9; jj++) m = fmaxf(m, sc[jj]);
    float sum = 0.f;
    #pragma unroll
    for (int jj = 0; jj < 9; jj++) { sc[jj] = __expf(sc[jj] - m); sum += sc[jj]; }
    const float inv = 1.f / sum;

    float out[16];
    #pragma unroll
    for (int hd = 0; hd < 16; hd++) out[hd] = 0.f;

    #pragma unroll
    for (int jj = 0; jj < 9; jj++) {
        int di = jj / 3 - 1, dj = jj % 3 - 1;
        int rr = r + di * d, cc = c + dj * d;
        if (rr >= 0 && rr < 80 && cc >= 0 && cc < 80) {
            int off = di * d * 80 + dj * d;
            float p = sc[jj] * inv;
            #pragma unroll
            for (int hd = 0; hd < 16; hd++)
                out[hd] = fmaf(p, vb[hd * NPIX + off], out[hd]);
        }
    }

    float* ob = g_attn + ((size_t)(b * 256 + dil * 128 + head * 32 + hd0)) * NPIX + n;
    #pragma unroll
    for (int hd = 0; hd < 16; hd++)
        ob[hd * NPIX] = __uint_as_float(f2tf32(out[hd]));
}

// ---------------------------------------------------------------------------
// Kernel C: out[b][n][o] = sum_c w_proj[o][c]*attn[b][c][n] + b_proj[o] + resid
// ---------------------------------------------------------------------------
__global__ __launch_bounds__(256, 2) void proj_kernel(const float* __restrict__ bias,
                                                      const float* __restrict__ rgb,
                                                      const float* __restrict__ ir,
                                                      float* __restrict__ out)
{
    __shared__ __align__(16) float buf[2 * STAGE_F];

    const int b  = blockIdx.z;
    const int n0 = blockIdx.x * 128;
    const int m0 = blockIdx.y * 128;
    const int tid = threadIdx.x;
    const int wid = tid >> 5, lane = tid & 31;
    const int wm0 = (wid >> 2) * 64, wn0 = (wid & 3) * 32;
    const int row = lane >> 2, colk = lane & 3;

    const float* ab = g_attn + (size_t)b * 256 * NPIX;

    const int am0 = (tid) >> 2,        akc0 = (tid) & 3;
    const int am1 = (tid + 256) >> 2,  akc1 = (tid + 256) & 3;
    const int bk0 = (tid) >> 5,        bnc0 = (tid) & 31;
    const int bk1 = (tid + 256) >> 5,  bnc1 = (tid + 256) & 31;

    const uint32_t sbase = smem_u32(buf);

    auto load_tile = [&](int kt, int stage) {
        const int k0 = kt * 16;
        const uint32_t As = sbase + stage * STAGE_F * 4;
        const uint32_t Bs = As + AS_SIZE * 4;
        cp16(As + (am0 * AS_STRIDE + akc0 * 4) * 4, g_wp + (size_t)(m0 + am0) * 256 + k0 + akc0 * 4);
        cp16(As + (am1 * AS_STRIDE + akc1 * 4) * 4, g_wp + (size_t)(m0 + am1) * 256 + k0 + akc1 * 4);
        cp16(Bs + (bk0 * BS_STRIDE + bnc0 * 4) * 4, ab + (size_t)(k0 + bk0) * NPIX + n0 + bnc0 * 4);
        cp16(Bs + (bk1 * BS_STRIDE + bnc1 * 4) * 4, ab + (size_t)(k0 + bk1) * NPIX + n0 + bnc1 * 4);
    };

    float acc[4][4][4];
    #pragma unroll
    for (int mt = 0; mt < 4; mt++)
        #pragma unroll
        for (int nt = 0; nt < 4; nt++)
            #pragma unroll
            for (int i = 0; i < 4; i++) acc[mt][nt][i] = 0.f;

    load_tile(0, 0); CP_COMMIT();
    load_tile(1, 1); CP_COMMIT();

    for (int kt = 0; kt < 16; kt++) {
        CP_WAIT1();
        __syncthreads();
        const float* As = buf + (kt & 1) * STAGE_F;
        const float* Bs = As + AS_SIZE;
        gemm_ktile<false>(As, Bs, wm0, wn0, row, colk, acc);
        __syncthreads();
        if (kt + 2 < 16) load_tile(kt + 2, kt & 1);
        CP_COMMIT();
    }

    // Epilogue: + bias + residual, write out[b][n][o] (o contiguous)
    const float* resb = ((m0 == 0) ? rgb : ir) + (size_t)b * 128 * NPIX;
    float* outb = out + (size_t)b * NPIX * 256;

    #pragma unroll
    for (int mt = 0; mt < 4; mt++) {
        const int o_lo = m0 + wm0 + mt * 16 + row;
        const int o_hi = o_lo + 8;
        const float bias_lo = __ldg(bias + o_lo);
        const float bias_hi = __ldg(bias + o_hi);
        const float* res_lo = resb + (size_t)(o_lo & 127) * NPIX;
        const float* res_hi = resb + (size_t)(o_hi & 127) * NPIX;
        #pragma unroll
        for (int nt = 0; nt < 4; nt++) {
            const int n = n0 + wn0 + nt * 8 + 2 * colk;
            outb[(size_t)n * 256 + o_lo]       = acc[mt][nt][0] + bias_lo + res_lo[n];
            outb[(size_t)(n + 1) * 256 + o_lo] = acc[mt][nt][1] + bias_lo + res_lo[n + 1];
            outb[(size_t)n * 256 + o_hi]       = acc[mt][nt][2] + bias_hi + res_hi[n];
            outb[(size_t)(n + 1) * 256 + o_hi] = acc[mt][nt][3] + bias_hi + res_hi[n + 1];
        }
    }
}

// ---------------------------------------------------------------------------
extern "C" void kernel_launch(void* const* d_in, const int* in_sizes, int n_in,
                              void* d_out, int out_size)
{
    const float* rgb    = (const float*)d_in[0];
    const float* ir     = (const float*)d_in[1];
    const float* w_qkv  = (const float*)d_in[2];
    const float* w_proj = (const float*)d_in[3];
    const float* b_proj = (const float*)d_in[4];
    float* out = (float*)d_out;

    conv_w<<<1024, 256>>>(w_qkv, w_proj);
    qkv_gemm<<<dim3(50, 6, 4), 256>>>(rgb, ir);
    attn_kernel<<<dim3(50, 8, 4), 256>>>();
    proj_kernel<<<dim3(50, 2, 4), 256>>>(b_proj, rgb, ir, out);
}

// round 9
// speedup vs baseline: 1.5321x; 1.0292x over previous
#include <cuda_runtime.h>
#include <cstdint>

#define NPIX   6400
#define SCALE  0.17677669529663687f   // 32^-0.5

// Scratch (device globals), channel-major layouts. g_qkv padded +16 for the
// attn vector-load overread at OOB-masked components.
__device__ float g_qkv [4 * 768 * 6400 + 16];  // [b][o][n]  fp32
__device__ float g_attn[4 * 256 * 6400];       // [b][ch][n] tf32 bits
__device__ float g_wq  [768 * 256];            // w_qkv, tf32, k-interleaved
__device__ float g_wp  [256 * 256];            // w_proj, tf32, k-interleaved

// ---------------------------------------------------------------------------
// Helpers (sm_80-class PTX only: family-safe on compute_103)
// ---------------------------------------------------------------------------
__device__ __forceinline__ uint32_t smem_u32(const void* p) {
    uint32_t a;
    asm("{ .reg .u64 t; cvta.to.shared.u64 t, %1; cvt.u32.u64 %0, t; }" : "=r"(a) : "l"(p));
    return a;
}
__device__ __forceinline__ void cp16(uint32_t dst, const void* src) {
    asm volatile("cp.async.cg.shared.global [%0], [%1], 16;" :: "r"(dst), "l"(src));
}
#define CP_COMMIT() asm volatile("cp.async.commit_group;" ::: "memory")
#define CP_WAIT1()  asm volatile("cp.async.wait_group 1;" ::: "memory")

__device__ __forceinline__ uint32_t f2tf32(float x) {
    uint32_t u;
    asm("cvt.rna.tf32.f32 %0, %1;" : "=r"(u) : "f"(x));
    return u;
}
__device__ __forceinline__ void mma_tf32(float c[4],
                                         uint32_t a0, uint32_t a1, uint32_t a2, uint32_t a3,
                                         uint32_t b0, uint32_t b1) {
    asm volatile("mma.sync.aligned.m16n8k8.row.col.f32.tf32.tf32.f32 "
                 "{%0,%1,%2,%3}, {%4,%5,%6,%7}, {%8,%9}, {%0,%1,%2,%3};"
                 : "+f"(c[0]), "+f"(c[1]), "+f"(c[2]), "+f"(c[3])
                 : "r"(a0), "r"(a1), "r"(a2), "r"(a3), "r"(b0), "r"(b1));
}

// Smem (per stage): A [128 m][40] floats (32 k interleaved + pad), B [32 k][136]
#define AS_STRIDE 40
#define AS_SIZE   (128 * AS_STRIDE)      // 5120 floats
#define BS_STRIDE 136
#define BS_SIZE   (32 * BS_STRIDE)       // 4352 floats
#define STAGE_F   (AS_SIZE + BS_SIZE)    // 9472 floats
#define SMEM_BYTES (2 * STAGE_F * 4)     // 75776 bytes

// ---------------------------------------------------------------------------
// Weight prologue: tf32-rounded + k-interleaved within each 8-block
// ---------------------------------------------------------------------------
__global__ __launch_bounds__(256) void conv_w(const float* __restrict__ wq,
                                              const float* __restrict__ wp)
{
    const int row = blockIdx.x;          // 0..1023 : 0..767 wq, 768..1023 wp
    const int k   = threadIdx.x;
    const int kp  = (k & ~7) | (((k & 3) << 1) | ((k >> 2) & 1));
    if (row < 768) {
        g_wq[row * 256 + kp] = __uint_as_float(f2tf32(wq[row * 256 + k]));
    } else {
        int r = row - 768;
        g_wp[r * 256 + kp] = __uint_as_float(f2tf32(wp[r * 256 + k]));
    }
}

// ---------------------------------------------------------------------------
// GEMM k-tile (32 k): warp grid 2(m) x 4(n), warp tile 64 x 32.
// ---------------------------------------------------------------------------
template <bool CVT_B>
__device__ __forceinline__ void gemm_ktile(const float* As, const float* Bs,
                                           int wm0, int wn0, int row, int colk,
                                           float acc[4][4][4]) {
    #pragma unroll
    for (int ks = 0; ks < 4; ks++) {
        const int kb = ks * 8;
        uint32_t a[4][4], bfr[4][2];
        #pragma unroll
        for (int mt = 0; mt < 4; mt++) {
            const float* ab = As + (wm0 + mt * 16 + row) * AS_STRIDE + kb + 2 * colk;
            float2 lo = *(const float2*)ab;
            float2 hi = *(const float2*)(ab + 8 * AS_STRIDE);
            a[mt][0] = __float_as_uint(lo.x);
            a[mt][1] = __float_as_uint(hi.x);
            a[mt][2] = __float_as_uint(lo.y);
            a[mt][3] = __float_as_uint(hi.y);
        }
        #pragma unroll
        for (int nt = 0; nt < 4; nt++) {
            const float* bb = Bs + (kb + colk) * BS_STRIDE + wn0 + nt * 8 + row;
            if (CVT_B) {
                bfr[nt][0] = f2tf32(bb[0]);
                bfr[nt][1] = f2tf32(bb[4 * BS_STRIDE]);
            } else {
                bfr[nt][0] = __float_as_uint(bb[0]);
                bfr[nt][1] = __float_as_uint(bb[4 * BS_STRIDE]);
            }
        }
        #pragma unroll
        for (int mt = 0; mt < 4; mt++)
            #pragma unroll
            for (int nt = 0; nt < 4; nt++)
                mma_tf32(acc[mt][nt], a[mt][0], a[mt][1], a[mt][2], a[mt][3],
                         bfr[nt][0], bfr[nt][1]);
    }
}

// ---------------------------------------------------------------------------
// Kernel A: qkv[b][o][n] = sum_c w_qkv[o][c] * y[b][c][n]
// ---------------------------------------------------------------------------
__global__ __launch_bounds__(256, 2) void qkv_gemm(const float* __restrict__ rgb,
                                                   const float* __restrict__ ir)
{
    extern __shared__ __align__(16) float buf[];

    const int b  = blockIdx.z;
    const int n0 = blockIdx.x * 128;
    const int m0 = blockIdx.y * 128;
    const int tid = threadIdx.x;
    const int wid = tid >> 5, lane = tid & 31;
    const int wm0 = (wid >> 2) * 64, wn0 = (wid & 3) * 32;
    const int row = lane >> 2, colk = lane & 3;

    const float* rb = rgb + (size_t)b * 128 * NPIX;
    const float* ib = ir  + (size_t)b * 128 * NPIX;

    const uint32_t sbase = smem_u32(buf);

    auto load_tile = [&](int kt, int stage) {
        const int k0 = kt * 32;
        const uint32_t As = sbase + stage * STAGE_F * 4;
        const uint32_t Bs = As + AS_SIZE * 4;
        #pragma unroll
        for (int j = 0; j < 4; j++) {
            int idx = tid + 256 * j;
            int ar = idx >> 3, ap = (idx & 7) * 4;     // A: 128 rows x 8 chunks
            cp16(As + (ar * AS_STRIDE + ap) * 4, g_wq + (size_t)(m0 + ar) * 256 + k0 + ap);
        }
        #pragma unroll
        for (int j = 0; j < 4; j++) {
            int idx = tid + 256 * j;
            int bk = idx >> 5, bnc = (idx & 31) * 4;   // B: 32 rows x 32 chunks
            int cc = k0 + bk;
            const float* s = (cc < 128) ? (rb + (size_t)cc * NPIX) : (ib + (size_t)(cc - 128) * NPIX);
            cp16(Bs + (bk * BS_STRIDE + bnc) * 4, s + n0 + bnc);
        }
    };

    float acc[4][4][4];
    #pragma unroll
    for (int mt = 0; mt < 4; mt++)
        #pragma unroll
        for (int nt = 0; nt < 4; nt++)
            #pragma unroll
            for (int i = 0; i < 4; i++) acc[mt][nt][i] = 0.f;

    load_tile(0, 0); CP_COMMIT();
    load_tile(1, 1); CP_COMMIT();

    for (int kt = 0; kt < 8; kt++) {
        CP_WAIT1();
        __syncthreads();
        const float* As = buf + (kt & 1) * STAGE_F;
        const float* Bs = As + AS_SIZE;
        gemm_ktile<true>(As, Bs, wm0, wn0, row, colk, acc);
        __syncthreads();
        if (kt + 2 < 8) load_tile(kt + 2, kt & 1);
        CP_COMMIT();
    }

    float* outb = g_qkv + (size_t)b * 768 * NPIX;
    #pragma unroll
    for (int mt = 0; mt < 4; mt++) {
        #pragma unroll
        for (int nt = 0; nt < 4; nt++) {
            int o = m0 + wm0 + mt * 16 + row;
            int n = n0 + wn0 + nt * 8 + 2 * colk;
            *(float2*)(outb + (size_t)o * NPIX + n) =
                make_float2(acc[mt][nt][0], acc[mt][nt][1]);
            *(float2*)(outb + (size_t)(o + 8) * NPIX + n) =
                make_float2(acc[mt][nt][2], acc[mt][nt][3]);
        }
    }
}

// ---------------------------------------------------------------------------
// Kernel B: dilated local attention, 2 pixels/thread (float2), hd split in
// half across lane pairs (xor 16). OOB components -> exact logit 0.
// ---------------------------------------------------------------------------
__global__ __launch_bounds__(256) void attn_kernel()
{
    const int tid  = threadIdx.x;
    const int wid  = tid >> 5, lane = tid & 31;
    const int half = lane >> 4;
    const int pp   = blockIdx.x * 128 + wid * 16 + (lane & 15);  // pixel-pair idx
    const int n    = pp * 2;
    const int dh   = blockIdx.y;
    const int dil  = dh >> 2;
    const int head = dh & 3;
    const int b    = blockIdx.z;
    const int d    = dil ? 3 : 2;

    const int r = n / 80;
    const int c = n % 80;          // even; both pixels in same row
    const int hd0 = half * 16;

    const float* qb = g_qkv + ((size_t)(b * 768 + dil * 128 + head * 32 + hd0)) * NPIX + n;
    const float* kb = qb + (size_t)256 * NPIX;
    const float* vb = qb + (size_t)512 * NPIX;

    float2 q[16];
    #pragma unroll
    for (int hd = 0; hd < 16; hd++) q[hd] = *(const float2*)(qb + hd * NPIX);

    float scx[9], scy[9];
    #pragma unroll
    for (int jj = 0; jj < 9; jj++) {
        const int di = jj / 3 - 1, dj = jj % 3 - 1;
        const int rr = r + di * d;
        const int cc0 = c + dj * d, cc1 = cc0 + 1;
        const bool v0 = (cc0 >= 0 && cc0 < 80);
        const bool v1 = (cc1 >= 0 && cc1 < 80);
        float sx = 0.f, sy = 0.f;
        if (rr >= 0 && rr < 80 && (v0 || v1)) {
            const int off = di * d * 80 + dj * d;
            const float* kp = kb + off;
            if ((off & 1) == 0) {                     // 8B-aligned vector path
                #pragma unroll
                for (int hd = 0; hd < 16; hd++) {
                    float2 kv = *(const float2*)(kp + hd * NPIX);
                    sx = fmaf(q[hd].x, kv.x, sx);
                    sy = fmaf(q[hd].y, kv.y, sy);
                }
            } else {                                  // odd offset: scalar pair
                #pragma unroll
                for (int hd = 0; hd < 16; hd++) {
                    sx = fmaf(q[hd].x, kp[hd * NPIX], sx);
                    sy = fmaf(q[hd].y, kp[hd * NPIX + 1], sy);
                }
            }
            if (!v0) sx = 0.f;
            if (!v1) sy = 0.f;
        }
        // combine hd halves (uniform across lane pairs: same pixel, same branch)
        sx += __shfl_xor_sync(0xFFFFFFFFu, sx, 16);
        sy += __shfl_xor_sync(0xFFFFFFFFu, sy, 16);
        scx[jj] = sx * SCALE;
        scy[jj] = sy * SCALE;
    }

    float mx = scx[0], my = scy[0];
    #pragma unroll
    for (int jj = 1; jj < 9; jj++) { mx = fmaxf(mx, scx[jj]); my = fmaxf(my, scy[jj]); }
    float sumx = 0.f, sumy = 0.f;
    #pragma unroll
    for (int jj = 0; jj < 9; jj++) {
        scx[jj] = __expf(scx[jj] - mx); sumx += scx[jj];
        scy[jj] = __expf(scy[jj] - my); sumy += scy[jj];
    }
    const float invx = 1.f / sumx, invy = 1.f / sumy;

    float2 out[16];
    #pragma unroll
    for (int hd = 0; hd < 16; hd++) out[hd] = make_float2(0.f, 0.f);

    #pragma unroll
    for (int jj = 0; jj < 9; jj++) {
        const int di = jj / 3 - 1, dj = jj % 3 - 1;
        const int rr = r + di * d;
        const int cc0 = c + dj * d, cc1 = cc0 + 1;
        const bool v0 = (cc0 >= 0 && cc0 < 80);
        const bool v1 = (cc1 >= 0 && cc1 < 80);
        if (rr >= 0 && rr < 80 && (v0 || v1)) {
            const int off = di * d * 80 + dj * d;
            const float px = v0 ? scx[jj] * invx : 0.f;
            const float py = v1 ? scy[jj] * invy : 0.f;
            const float* vp = vb + off;
            if ((off & 1) == 0) {
                #pragma unroll
                for (int hd = 0; hd < 16; hd++) {
                    float2 vv = *(const float2*)(vp + hd * NPIX);
                    out[hd].x = fmaf(px, vv.x, out[hd].x);
                    out[hd].y = fmaf(py, vv.y, out[hd].y);
                }
            } else {
                #pragma unroll
                for (int hd = 0; hd < 16; hd++) {
                    out[hd].x = fmaf(px, vp[hd * NPIX], out[hd].x);
                    out[hd].y = fmaf(py, vp[hd * NPIX + 1], out[hd].y);
                }
            }
        }
    }

    float* ob = g_attn + ((size_t)(b * 256 + dil * 128 + head * 32 + hd0)) * NPIX + n;
    #pragma unroll
    for (int hd = 0; hd < 16; hd++) {
        float2 o2 = make_float2(__uint_as_float(f2tf32(out[hd].x)),
                                __uint_as_float(f2tf32(out[hd].y)));
        *(float2*)(ob + hd * NPIX) = o2;
    }
}

// ---------------------------------------------------------------------------
// Kernel C: out[b][n][o] = sum_c w_proj[o][c]*attn[b][c][n] + b_proj[o] + resid
// ---------------------------------------------------------------------------
__global__ __launch_bounds__(256, 2) void proj_kernel(const float* __restrict__ bias,
                                                      const float* __restrict__ rgb,
                                                      const float* __restrict__ ir,
                                                      float* __restrict__ out)
{
    extern __shared__ __align__(16) float buf[];

    const int b  = blockIdx.z;
    const int n0 = blockIdx.x * 128;
    const int m0 = blockIdx.y * 128;
    const int tid = threadIdx.x;
    const int wid = tid >> 5, lane = tid & 31;
    const int wm0 = (wid >> 2) * 64, wn0 = (wid & 3) * 32;
    const int row = lane >> 2, colk = lane & 3;

    const float* ab = g_attn + (size_t)b * 256 * NPIX;
    const uint32_t sbase = smem_u32(buf);

    auto load_tile = [&](int kt, int stage) {
        const int k0 = kt * 32;
        const uint32_t As = sbase + stage * STAGE_F * 4;
        const uint32_t Bs = As + AS_SIZE * 4;
        #pragma unroll
        for (int j = 0; j < 4; j++) {
            int idx = tid + 256 * j;
            int ar = idx >> 3, ap = (idx & 7) * 4;
            cp16(As + (ar * AS_STRIDE + ap) * 4, g_wp + (size_t)(m0 + ar) * 256 + k0 + ap);
        }
        #pragma unroll
        for (int j = 0; j < 4; j++) {
            int idx = tid + 256 * j;
            int bk = idx >> 5, bnc = (idx & 31) * 4;
            cp16(Bs + (bk * BS_STRIDE + bnc) * 4, ab + (size_t)(k0 + bk) * NPIX + n0 + bnc);
        }
    };

    float acc[4][4][4];
    #pragma unroll
    for (int mt = 0; mt < 4; mt++)
        #pragma unroll
        for (int nt = 0; nt < 4; nt++)
            #pragma unroll
            for (int i = 0; i < 4; i++) acc[mt][nt][i] = 0.f;

    load_tile(0, 0); CP_COMMIT();
    load_tile(1, 1); CP_COMMIT();

    for (int kt = 0; kt < 8; kt++) {
        CP_WAIT1();
        __syncthreads();
        const float* As = buf + (kt & 1) * STAGE_F;
        const float* Bs = As + AS_SIZE;
        gemm_ktile<false>(As, Bs, wm0, wn0, row, colk, acc);
        __syncthreads();
        if (kt + 2 < 8) load_tile(kt + 2, kt & 1);
        CP_COMMIT();
    }

    const float* resb = ((m0 == 0) ? rgb : ir) + (size_t)b * 128 * NPIX;
    float* outb = out + (size_t)b * NPIX * 256;

    #pragma unroll
    for (int mt = 0; mt < 4; mt++) {
        const int o_lo = m0 + wm0 + mt * 16 + row;
        const int o_hi = o_lo + 8;
        const float bias_lo = __ldg(bias + o_lo);
        const float bias_hi = __ldg(bias + o_hi);
        const float* res_lo = resb + (size_t)(o_lo & 127) * NPIX;
        const float* res_hi = resb + (size_t)(o_hi & 127) * NPIX;
        #pragma unroll
        for (int nt = 0; nt < 4; nt++) {
            const int n = n0 + wn0 + nt * 8 + 2 * colk;
            outb[(size_t)n * 256 + o_lo]       = acc[mt][nt][0] + bias_lo + res_lo[n];
            outb[(size_t)(n + 1) * 256 + o_lo] = acc[mt][nt][1] + bias_lo + res_lo[n + 1];
            outb[(size_t)n * 256 + o_hi]       = acc[mt][nt][2] + bias_hi + res_hi[n];
            outb[(size_t)(n + 1) * 256 + o_hi] = acc[mt][nt][3] + bias_hi + res_hi[n + 1];
        }
    }
}

// ---------------------------------------------------------------------------
extern "C" void kernel_launch(void* const* d_in, const int* in_sizes, int n_in,
                              void* d_out, int out_size)
{
    const float* rgb    = (const float*)d_in[0];
    const float* ir     = (const float*)d_in[1];
    const float* w_qkv  = (const float*)d_in[2];
    const float* w_proj = (const float*)d_in[3];
    const float* b_proj = (const float*)d_in[4];
    float* out = (float*)d_out;

    // Opt-in dynamic smem (>48KB). Host-side, idempotent, capture-safe.
    cudaFuncSetAttribute(qkv_gemm, cudaFuncAttributeMaxDynamicSharedMemorySize, SMEM_BYTES);
    cudaFuncSetAttribute(proj_kernel, cudaFuncAttributeMaxDynamicSharedMemorySize, SMEM_BYTES);

    conv_w<<<1024, 256>>>(w_qkv, w_proj);
    qkv_gemm<<<dim3(50, 6, 4), 256, SMEM_BYTES>>>(rgb, ir);
    attn_kernel<<<dim3(25, 8, 4), 256>>>();
    proj_kernel<<<dim3(50, 2, 4), 256, SMEM_BYTES>>>(b_proj, rgb, ir, out);
}

// round 10
// speedup vs baseline: 2.0124x; 1.3135x over previous
#include <cuda_runtime.h>
#include <cstdint>
#include <cuda_fp16.h>

#define NPIX   6400
#define SCALE  0.17677669529663687f   // 32^-0.5

// Scratch (device globals). g_qkv padded +16 for attn vector overread.
__device__ float    g_qkv   [4 * 768 * 6400 + 16];  // [b][o][n] fp32
__device__ uint32_t g_attn16[4 * 128 * 6400];       // [b][c2][n] half2 words
__device__ uint32_t g_y16   [4 * 128 * 6400];       // [b][c2][n] half2 words
__device__ uint32_t g_wq16  [768 * 128];            // packed fp16, interleaved
__device__ uint32_t g_wp16  [256 * 128];            // packed fp16, interleaved

// ---------------------------------------------------------------------------
// Helpers (sm_80-class PTX only: family-safe on compute_103)
// ---------------------------------------------------------------------------
__device__ __forceinline__ uint32_t smem_u32(const void* p) {
    uint32_t a;
    asm("{ .reg .u64 t; cvta.to.shared.u64 t, %1; cvt.u32.u64 %0, t; }" : "=r"(a) : "l"(p));
    return a;
}
__device__ __forceinline__ void cp16(uint32_t dst, const void* src) {
    asm volatile("cp.async.cg.shared.global [%0], [%1], 16;" :: "r"(dst), "l"(src));
}
#define CP_COMMIT() asm volatile("cp.async.commit_group;" ::: "memory")
#define CP_WAIT1()  asm volatile("cp.async.wait_group 1;" ::: "memory")

__device__ __forceinline__ uint32_t packh2(float a, float b) {
    __half2 h = __floats2half2_rn(a, b);          // a -> low half (k even)
    return *reinterpret_cast<uint32_t*>(&h);
}
__device__ __forceinline__ void mma_f16(float c[4],
                                        uint32_t a0, uint32_t a1, uint32_t a2, uint32_t a3,
                                        uint32_t b0, uint32_t b1) {
    asm volatile("mma.sync.aligned.m16n8k16.row.col.f32.f16.f16.f32 "
                 "{%0,%1,%2,%3}, {%4,%5,%6,%7}, {%8,%9}, {%0,%1,%2,%3};"
                 : "+f"(c[0]), "+f"(c[1]), "+f"(c[2]), "+f"(c[3])
                 : "r"(a0), "r"(a1), "r"(a2), "r"(a3), "r"(b0), "r"(b1));
}

// Smem (per stage, uint32 words): A [128 o][24] (16 words + pad), B [16][136]
#define AS_W    24
#define AS_SZ   (128 * AS_W)             // 3072 words
#define BS_W    136
#define BS_SZ   (16 * BS_W)              // 2176 words
#define STAGE_W (AS_SZ + BS_SZ)          // 5248 words; x2 stages = 41984 B

// ---------------------------------------------------------------------------
// Prologue 1: weights -> packed fp16 words, 8-group interleaved.
// word j of row o = half2(w[o][2j], w[o][2j+1]); stored at
// jp = (j&~7) | ((j&3)<<1) | ((j>>2)&1)   (so (colk, colk+4) become adjacent)
// ---------------------------------------------------------------------------
__global__ __launch_bounds__(128) void conv_w(const float* __restrict__ wq,
                                              const float* __restrict__ wp)
{
    const int row = blockIdx.x;          // 0..1023 : 0..767 wq, 768..1023 wp
    const int j   = threadIdx.x;         // word 0..127
    const int jp  = (j & ~7) | (((j & 3) << 1) | ((j >> 2) & 1));
    if (row < 768) {
        uint32_t v = packh2(wq[row * 256 + 2 * j], wq[row * 256 + 2 * j + 1]);
        g_wq16[row * 128 + jp] = v;
    } else {
        int r = row - 768;
        uint32_t v = packh2(wp[r * 256 + 2 * j], wp[r * 256 + 2 * j + 1]);
        g_wp16[r * 128 + jp] = v;
    }
}

// ---------------------------------------------------------------------------
// Prologue 2: y = concat(rgb, ir) -> packed fp16 words [b][c2][n]
// ---------------------------------------------------------------------------
__global__ __launch_bounds__(256) void conv_y16(const float* __restrict__ rgb,
                                                const float* __restrict__ ir)
{
    const int n  = blockIdx.x * 256 + threadIdx.x;
    const int c2 = blockIdx.y;           // 0..127
    const int b  = blockIdx.z;
    const float* src = (c2 < 64)
        ? rgb + ((size_t)b * 128 + 2 * c2) * NPIX
        : ir  + ((size_t)b * 128 + 2 * (c2 - 64)) * NPIX;
    g_y16[((size_t)b * 128 + c2) * NPIX + n] = packh2(src[n], src[NPIX + n]);
}

// ---------------------------------------------------------------------------
// GEMM k-tile (32 k = 16 words): warp grid 2(m) x 4(n), warp tile 64 x 32.
// ---------------------------------------------------------------------------
__device__ __forceinline__ void gemm_ktile16(const uint32_t* As, const uint32_t* Bs,
                                             int wm0, int wn0, int row, int colk,
                                             float acc[4][4][4]) {
    #pragma unroll
    for (int ks = 0; ks < 2; ks++) {
        const int kb = ks * 8;
        uint32_t a[4][4], bfr[4][2];
        #pragma unroll
        for (int mt = 0; mt < 4; mt++) {
            const uint32_t* ab = As + (wm0 + mt * 16 + row) * AS_W + kb + 2 * colk;
            uint2 lo = *(const uint2*)ab;              // words (colk, colk+4)
            uint2 hi = *(const uint2*)(ab + 8 * AS_W); // row+8
            a[mt][0] = lo.x;   // k 0..7 pair, row
            a[mt][1] = hi.x;   // k 0..7 pair, row+8
            a[mt][2] = lo.y;   // k 8..15 pair, row
            a[mt][3] = hi.y;   // k 8..15 pair, row+8
        }
        #pragma unroll
        for (int nt = 0; nt < 4; nt++) {
            const uint32_t* bb = Bs + (kb + colk) * BS_W + wn0 + nt * 8 + row;
            bfr[nt][0] = bb[0];
            bfr[nt][1] = bb[4 * BS_W];
        }
        #pragma unroll
        for (int mt = 0; mt < 4; mt++)
            #pragma unroll
            for (int nt = 0; nt < 4; nt++)
                mma_f16(acc[mt][nt], a[mt][0], a[mt][1], a[mt][2], a[mt][3],
                        bfr[nt][0], bfr[nt][1]);
    }
}

// ---------------------------------------------------------------------------
// Kernel A: qkv[b][o][n] = sum_c w_qkv[o][c] * y[b][c][n]   (fp16 MMA)
// ---------------------------------------------------------------------------
__global__ __launch_bounds__(256, 2) void qkv_gemm()
{
    __shared__ __align__(16) uint32_t buf[2 * STAGE_W];

    const int b  = blockIdx.z;
    const int n0 = blockIdx.x * 128;
    const int m0 = blockIdx.y * 128;
    const int tid = threadIdx.x;
    const int wid = tid >> 5, lane = tid & 31;
    const int wm0 = (wid >> 2) * 64, wn0 = (wid & 3) * 32;
    const int row = lane >> 2, colk = lane & 3;

    const uint32_t* yb = g_y16 + (size_t)b * 128 * NPIX;
    const uint32_t sbase = smem_u32(buf);

    auto load_tile = [&](int kt, int stage) {
        const int kw0 = kt * 16;                       // word-k base
        const uint32_t As = sbase + stage * STAGE_W * 4;
        const uint32_t Bs = As + AS_SZ * 4;
        #pragma unroll
        for (int j = 0; j < 2; j++) {
            int idx = tid + 256 * j;
            int ar = idx >> 2, ac = (idx & 3) * 4;     // A: 128 rows x 4 chunks
            cp16(As + (ar * AS_W + ac) * 4, g_wq16 + (size_t)(m0 + ar) * 128 + kw0 + ac);
        }
        #pragma unroll
        for (int j = 0; j < 2; j++) {
            int idx = tid + 256 * j;
            int bk = idx >> 5, bnc = (idx & 31) * 4;   // B: 16 rows x 32 chunks
            cp16(Bs + (bk * BS_W + bnc) * 4, yb + (size_t)(kw0 + bk) * NPIX + n0 + bnc);
        }
    };

    float acc[4][4][4];
    #pragma unroll
    for (int mt = 0; mt < 4; mt++)
        #pragma unroll
        for (int nt = 0; nt < 4; nt++)
            #pragma unroll
            for (int i = 0; i < 4; i++) acc[mt][nt][i] = 0.f;

    load_tile(0, 0); CP_COMMIT();
    load_tile(1, 1); CP_COMMIT();

    for (int kt = 0; kt < 8; kt++) {
        CP_WAIT1();
        __syncthreads();
        const uint32_t* As = buf + (kt & 1) * STAGE_W;
        const uint32_t* Bs = As + AS_SZ;
        gemm_ktile16(As, Bs, wm0, wn0, row, colk, acc);
        __syncthreads();
        if (kt + 2 < 8) load_tile(kt + 2, kt & 1);
        CP_COMMIT();
    }

    float* outb = g_qkv + (size_t)b * 768 * NPIX;
    #pragma unroll
    for (int mt = 0; mt < 4; mt++) {
        #pragma unroll
        for (int nt = 0; nt < 4; nt++) {
            int o = m0 + wm0 + mt * 16 + row;
            int n = n0 + wn0 + nt * 8 + 2 * colk;
            *(float2*)(outb + (size_t)o * NPIX + n) =
                make_float2(acc[mt][nt][0], acc[mt][nt][1]);
            *(float2*)(outb + (size_t)(o + 8) * NPIX + n) =
                make_float2(acc[mt][nt][2], acc[mt][nt][3]);
        }
    }
}

// ---------------------------------------------------------------------------
// Kernel B: dilated local attention, 2 pixels/thread (float2), hd halves
// across lane pairs (xor 16). Output: packed fp16 words (proj's B operand).
// ---------------------------------------------------------------------------
__global__ __launch_bounds__(256) void attn_kernel()
{
    const int tid  = threadIdx.x;
    const int wid  = tid >> 5, lane = tid & 31;
    const int half = lane >> 4;
    const int pp   = blockIdx.x * 128 + wid * 16 + (lane & 15);
    const int n    = pp * 2;
    const int dh   = blockIdx.y;
    const int dil  = dh >> 2;
    const int head = dh & 3;
    const int b    = blockIdx.z;
    const int d    = dil ? 3 : 2;

    const int r = n / 80;
    const int c = n % 80;
    const int hd0 = half * 16;

    const float* qb = g_qkv + ((size_t)(b * 768 + dil * 128 + head * 32 + hd0)) * NPIX + n;
    const float* kb = qb + (size_t)256 * NPIX;
    const float* vb = qb + (size_t)512 * NPIX;

    float2 q[16];
    #pragma unroll
    for (int hd = 0; hd < 16; hd++) q[hd] = *(const float2*)(qb + hd * NPIX);

    float scx[9], scy[9];
    #pragma unroll
    for (int jj = 0; jj < 9; jj++) {
        const int di = jj / 3 - 1, dj = jj % 3 - 1;
        const int rr = r + di * d;
        const int cc0 = c + dj * d, cc1 = cc0 + 1;
        const bool v0 = (cc0 >= 0 && cc0 < 80);
        const bool v1 = (cc1 >= 0 && cc1 < 80);
        float sx = 0.f, sy = 0.f;
        if (rr >= 0 && rr < 80 && (v0 || v1)) {
            const int off = di * d * 80 + dj * d;
            const float* kp = kb + off;
            if ((off & 1) == 0) {
                #pragma unroll
                for (int hd = 0; hd < 16; hd++) {
                    float2 kv = *(const float2*)(kp + hd * NPIX);
                    sx = fmaf(q[hd].x, kv.x, sx);
                    sy = fmaf(q[hd].y, kv.y, sy);
                }
            } else {
                #pragma unroll
                for (int hd = 0; hd < 16; hd++) {
                    sx = fmaf(q[hd].x, kp[hd * NPIX], sx);
                    sy = fmaf(q[hd].y, kp[hd * NPIX + 1], sy);
                }
            }
            if (!v0) sx = 0.f;
            if (!v1) sy = 0.f;
        }
        sx += __shfl_xor_sync(0xFFFFFFFFu, sx, 16);
        sy += __shfl_xor_sync(0xFFFFFFFFu, sy, 16);
        scx[jj] = sx * SCALE;
        scy[jj] = sy * SCALE;
    }

    float mx = scx[0], my = scy[0];
    #pragma unroll
    for (int jj = 1; jj < 9; jj++) { mx = fmaxf(mx, scx[jj]); my = fmaxf(my, scy[jj]); }
    float sumx = 0.f, sumy = 0.f;
    #pragma unroll
    for (int jj = 0; jj < 9; jj++) {
        scx[jj] = __expf(scx[jj] - mx); sumx += scx[jj];
        scy[jj] = __expf(scy[jj] - my); sumy += scy[jj];
    }
    const float invx = 1.f / sumx, invy = 1.f / sumy;

    float2 out[16];
    #pragma unroll
    for (int hd = 0; hd < 16; hd++) out[hd] = make_float2(0.f, 0.f);

    #pragma unroll
    for (int jj = 0; jj < 9; jj++) {
        const int di = jj / 3 - 1, dj = jj % 3 - 1;
        const int rr = r + di * d;
        const int cc0 = c + dj * d, cc1 = cc0 + 1;
        const bool v0 = (cc0 >= 0 && cc0 < 80);
        const bool v1 = (cc1 >= 0 && cc1 < 80);
        if (rr >= 0 && rr < 80 && (v0 || v1)) {
            const int off = di * d * 80 + dj * d;
            const float px = v0 ? scx[jj] * invx : 0.f;
            const float py = v1 ? scy[jj] * invy : 0.f;
            const float* vp = vb + off;
            if ((off & 1) == 0) {
                #pragma unroll
                for (int hd = 0; hd < 16; hd++) {
                    float2 vv = *(const float2*)(vp + hd * NPIX);
                    out[hd].x = fmaf(px, vv.x, out[hd].x);
                    out[hd].y = fmaf(py, vv.y, out[hd].y);
                }
            } else {
                #pragma unroll
                for (int hd = 0; hd < 16; hd++) {
                    out[hd].x = fmaf(px, vp[hd * NPIX], out[hd].x);
                    out[hd].y = fmaf(py, vp[hd * NPIX + 1], out[hd].y);
                }
            }
        }
    }

    // Packed fp16 words [b][c2][n]: word (c2, n) = half2(ch 2c2, ch 2c2+1)
    const int c2base = dil * 64 + head * 16 + half * 8;
    uint32_t* ob = g_attn16 + ((size_t)(b * 128 + c2base)) * NPIX + n;
    #pragma unroll
    for (int j = 0; j < 8; j++) {
        uint2 w;
        w.x = packh2(out[2 * j].x, out[2 * j + 1].x);   // pixel n
        w.y = packh2(out[2 * j].y, out[2 * j + 1].y);   // pixel n+1
        *(uint2*)(ob + (size_t)j * NPIX) = w;
    }
}

// ---------------------------------------------------------------------------
// Kernel C: out[b][n][o] = sum_c w_proj[o][c]*attn[b][c][n] + bias[o] + resid
// ---------------------------------------------------------------------------
__global__ __launch_bounds__(256, 2) void proj_kernel(const float* __restrict__ bias,
                                                      const float* __restrict__ rgb,
                                                      const float* __restrict__ ir,
                                                      float* __restrict__ out)
{
    __shared__ __align__(16) uint32_t buf[2 * STAGE_W];

    const int b  = blockIdx.z;
    const int n0 = blockIdx.x * 128;
    const int m0 = blockIdx.y * 128;
    const int tid = threadIdx.x;
    const int wid = tid >> 5, lane = tid & 31;
    const int wm0 = (wid >> 2) * 64, wn0 = (wid & 3) * 32;
    const int row = lane >> 2, colk = lane & 3;

    const uint32_t* ab = g_attn16 + (size_t)b * 128 * NPIX;
    const uint32_t sbase = smem_u32(buf);

    auto load_tile = [&](int kt, int stage) {
        const int kw0 = kt * 16;
        const uint32_t As = sbase + stage * STAGE_W * 4;
        const uint32_t Bs = As + AS_SZ * 4;
        #pragma unroll
        for (int j = 0; j < 2; j++) {
            int idx = tid + 256 * j;
            int ar = idx >> 2, ac = (idx & 3) * 4;
            cp16(As + (ar * AS_W + ac) * 4, g_wp16 + (size_t)(m0 + ar) * 128 + kw0 + ac);
        }
        #pragma unroll
        for (int j = 0; j < 2; j++) {
            int idx = tid + 256 * j;
            int bk = idx >> 5, bnc = (idx & 31) * 4;
            cp16(Bs + (bk * BS_W + bnc) * 4, ab + (size_t)(kw0 + bk) * NPIX + n0 + bnc);
        }
    };

    float acc[4][4][4];
    #pragma unroll
    for (int mt = 0; mt < 4; mt++)
        #pragma unroll
        for (int nt = 0; nt < 4; nt++)
            #pragma unroll
            for (int i = 0; i < 4; i++) acc[mt][nt][i] = 0.f;

    load_tile(0, 0); CP_COMMIT();
    load_tile(1, 1); CP_COMMIT();

    for (int kt = 0; kt < 8; kt++) {
        CP_WAIT1();
        __syncthreads();
        const uint32_t* As = buf + (kt & 1) * STAGE_W;
        const uint32_t* Bs = As + AS_SZ;
        gemm_ktile16(As, Bs, wm0, wn0, row, colk, acc);
        __syncthreads();
        if (kt + 2 < 8) load_tile(kt + 2, kt & 1);
        CP_COMMIT();
    }

    const float* resb = ((m0 == 0) ? rgb : ir) + (size_t)b * 128 * NPIX;
    float* outb = out + (size_t)b * NPIX * 256;

    #pragma unroll
    for (int mt = 0; mt < 4; mt++) {
        const int o_lo = m0 + wm0 + mt * 16 + row;
        const int o_hi = o_lo + 8;
        const float bias_lo = __ldg(bias + o_lo);
        const float bias_hi = __ldg(bias + o_hi);
        const float* res_lo = resb + (size_t)(o_lo & 127) * NPIX;
        const float* res_hi = resb + (size_t)(o_hi & 127) * NPIX;
        #pragma unroll
        for (int nt = 0; nt < 4; nt++) {
            const int n = n0 + wn0 + nt * 8 + 2 * colk;
            outb[(size_t)n * 256 + o_lo]       = acc[mt][nt][0] + bias_lo + res_lo[n];
            outb[(size_t)(n + 1) * 256 + o_lo] = acc[mt][nt][1] + bias_lo + res_lo[n + 1];
            outb[(size_t)n * 256 + o_hi]       = acc[mt][nt][2] + bias_hi + res_hi[n];
            outb[(size_t)(n + 1) * 256 + o_hi] = acc[mt][nt][3] + bias_hi + res_hi[n + 1];
        }
    }
}

// ---------------------------------------------------------------------------
extern "C" void kernel_launch(void* const* d_in, const int* in_sizes, int n_in,
                              void* d_out, int out_size)
{
    const float* rgb    = (const float*)d_in[0];
    const float* ir     = (const float*)d_in[1];
    const float* w_qkv  = (const float*)d_in[2];
    const float* w_proj = (const float*)d_in[3];
    const float* b_proj = (const float*)d_in[4];
    float* out = (float*)d_out;

    conv_w<<<1024, 128>>>(w_qkv, w_proj);
    conv_y16<<<dim3(25, 128, 4), 256>>>(rgb, ir);
    qkv_gemm<<<dim3(50, 6, 4), 256>>>();
    attn_kernel<<<dim3(25, 8, 4), 256>>>();
    proj_kernel<<<dim3(50, 2, 4), 256>>>(b_proj, rgb, ir, out);
}

// round 11
// speedup vs baseline: 2.3198x; 1.1528x over previous
#include <cuda_runtime.h>
#include <cstdint>
#include <cuda_fp16.h>

#define NPIX   6400
#define SCALE  0.17677669529663687f   // 32^-0.5

// Scratch (device globals), all fp16 channel-pair packed: word (c2, n) =
// half2(ch 2*c2, ch 2*c2+1) at pixel n. +16 words padding for vector overread.
__device__ __align__(16) uint32_t g_qkv16 [4 * 384 * 6400 + 16]; // q|k|v planes
__device__ __align__(16) uint32_t g_attn16[4 * 128 * 6400 + 16];
__device__ __align__(16) uint32_t g_y16   [4 * 128 * 6400];
__device__ uint32_t g_wq16[768 * 128];   // packed fp16, k-interleaved
__device__ uint32_t g_wp16[256 * 128];

// ---------------------------------------------------------------------------
// Helpers (sm_80-class PTX only: family-safe on compute_103)
// ---------------------------------------------------------------------------
__device__ __forceinline__ uint32_t smem_u32(const void* p) {
    uint32_t a;
    asm("{ .reg .u64 t; cvta.to.shared.u64 t, %1; cvt.u32.u64 %0, t; }" : "=r"(a) : "l"(p));
    return a;
}
__device__ __forceinline__ void cp16(uint32_t dst, const void* src) {
    asm volatile("cp.async.cg.shared.global [%0], [%1], 16;" :: "r"(dst), "l"(src));
}
#define CP_COMMIT() asm volatile("cp.async.commit_group;" ::: "memory")
#define CP_WAIT1()  asm volatile("cp.async.wait_group 1;" ::: "memory")

__device__ __forceinline__ uint32_t packh2(float a, float b) {
    __half2 h = __floats2half2_rn(a, b);          // a -> low half
    return *reinterpret_cast<uint32_t*>(&h);
}
__device__ __forceinline__ float2 unpackh2(uint32_t w) {
    return __half22float2(*reinterpret_cast<__half2*>(&w));
}
__device__ __forceinline__ void mma_f16(float c[4],
                                        uint32_t a0, uint32_t a1, uint32_t a2, uint32_t a3,
                                        uint32_t b0, uint32_t b1) {
    asm volatile("mma.sync.aligned.m16n8k16.row.col.f32.f16.f16.f32 "
                 "{%0,%1,%2,%3}, {%4,%5,%6,%7}, {%8,%9}, {%0,%1,%2,%3};"
                 : "+f"(c[0]), "+f"(c[1]), "+f"(c[2]), "+f"(c[3])
                 : "r"(a0), "r"(a1), "r"(a2), "r"(a3), "r"(b0), "r"(b1));
}

// Smem (per stage, uint32 words): A [128 o][24] (16 words + pad), B [16][136]
#define AS_W    24
#define AS_SZ   (128 * AS_W)
#define BS_W    136
#define BS_SZ   (16 * BS_W)
#define STAGE_W (AS_SZ + BS_SZ)

// ---------------------------------------------------------------------------
// Prologue 1: weights -> packed fp16 words, 8-group interleaved.
// ---------------------------------------------------------------------------
__global__ __launch_bounds__(128) void conv_w(const float* __restrict__ wq,
                                              const float* __restrict__ wp)
{
    const int row = blockIdx.x;          // 0..1023 : 0..767 wq, 768..1023 wp
    const int j   = threadIdx.x;
    const int jp  = (j & ~7) | (((j & 3) << 1) | ((j >> 2) & 1));
    if (row < 768) {
        g_wq16[row * 128 + jp] = packh2(wq[row * 256 + 2 * j], wq[row * 256 + 2 * j + 1]);
    } else {
        int r = row - 768;
        g_wp16[r * 128 + jp] = packh2(wp[r * 256 + 2 * j], wp[r * 256 + 2 * j + 1]);
    }
}

// ---------------------------------------------------------------------------
// Prologue 2: y = concat(rgb, ir) -> packed fp16 words [b][c2][n]
// ---------------------------------------------------------------------------
__global__ __launch_bounds__(256) void conv_y16(const float* __restrict__ rgb,
                                                const float* __restrict__ ir)
{
    const int n  = blockIdx.x * 256 + threadIdx.x;
    const int c2 = blockIdx.y;
    const int b  = blockIdx.z;
    const float* src = (c2 < 64)
        ? rgb + ((size_t)b * 128 + 2 * c2) * NPIX
        : ir  + ((size_t)b * 128 + 2 * (c2 - 64)) * NPIX;
    g_y16[((size_t)b * 128 + c2) * NPIX + n] = packh2(src[n], src[NPIX + n]);
}

// ---------------------------------------------------------------------------
// GEMM k-tile (32 k = 16 words): warp grid 2(m) x 4(n), warp tile 64 x 32.
// ---------------------------------------------------------------------------
__device__ __forceinline__ void gemm_ktile16(const uint32_t* As, const uint32_t* Bs,
                                             int wm0, int wn0, int row, int colk,
                                             float acc[4][4][4]) {
    #pragma unroll
    for (int ks = 0; ks < 2; ks++) {
        const int kb = ks * 8;
        uint32_t a[4][4], bfr[4][2];
        #pragma unroll
        for (int mt = 0; mt < 4; mt++) {
            const uint32_t* ab = As + (wm0 + mt * 16 + row) * AS_W + kb + 2 * colk;
            uint2 lo = *(const uint2*)ab;
            uint2 hi = *(const uint2*)(ab + 8 * AS_W);
            a[mt][0] = lo.x; a[mt][1] = hi.x; a[mt][2] = lo.y; a[mt][3] = hi.y;
        }
        #pragma unroll
        for (int nt = 0; nt < 4; nt++) {
            const uint32_t* bb = Bs + (kb + colk) * BS_W + wn0 + nt * 8 + row;
            bfr[nt][0] = bb[0];
            bfr[nt][1] = bb[4 * BS_W];
        }
        #pragma unroll
        for (int mt = 0; mt < 4; mt++)
            #pragma unroll
            for (int nt = 0; nt < 4; nt++)
                mma_f16(acc[mt][nt], a[mt][0], a[mt][1], a[mt][2], a[mt][3],
                        bfr[nt][0], bfr[nt][1]);
    }
}

// ---------------------------------------------------------------------------
// Kernel A: qkv (fp16 MMA) -> packed fp16 output via shfl pairing.
// ---------------------------------------------------------------------------
__global__ __launch_bounds__(256, 2) void qkv_gemm()
{
    __shared__ __align__(16) uint32_t buf[2 * STAGE_W];

    const int b  = blockIdx.z;
    const int n0 = blockIdx.x * 128;
    const int m0 = blockIdx.y * 128;
    const int tid = threadIdx.x;
    const int wid = tid >> 5, lane = tid & 31;
    const int wm0 = (wid >> 2) * 64, wn0 = (wid & 3) * 32;
    const int row = lane >> 2, colk = lane & 3;

    const uint32_t* yb = g_y16 + (size_t)b * 128 * NPIX;
    const uint32_t sbase = smem_u32(buf);

    auto load_tile = [&](int kt, int stage) {
        const int kw0 = kt * 16;
        const uint32_t As = sbase + stage * STAGE_W * 4;
        const uint32_t Bs = As + AS_SZ * 4;
        #pragma unroll
        for (int j = 0; j < 2; j++) {
            int idx = tid + 256 * j;
            int ar = idx >> 2, ac = (idx & 3) * 4;
            cp16(As + (ar * AS_W + ac) * 4, g_wq16 + (size_t)(m0 + ar) * 128 + kw0 + ac);
        }
        #pragma unroll
        for (int j = 0; j < 2; j++) {
            int idx = tid + 256 * j;
            int bk = idx >> 5, bnc = (idx & 31) * 4;
            cp16(Bs + (bk * BS_W + bnc) * 4, yb + (size_t)(kw0 + bk) * NPIX + n0 + bnc);
        }
    };

    float acc[4][4][4];
    #pragma unroll
    for (int mt = 0; mt < 4; mt++)
        #pragma unroll
        for (int nt = 0; nt < 4; nt++)
            #pragma unroll
            for (int i = 0; i < 4; i++) acc[mt][nt][i] = 0.f;

    load_tile(0, 0); CP_COMMIT();
    load_tile(1, 1); CP_COMMIT();

    for (int kt = 0; kt < 8; kt++) {
        CP_WAIT1();
        __syncthreads();
        const uint32_t* As = buf + (kt & 1) * STAGE_W;
        const uint32_t* Bs = As + AS_SZ;
        gemm_ktile16(As, Bs, wm0, wn0, row, colk, acc);
        __syncthreads();
        if (kt + 2 < 8) load_tile(kt + 2, kt & 1);
        CP_COMMIT();
    }

    // Epilogue: pair adjacent o rows via shfl, write packed fp16 [b][c2][n].
    uint32_t* outb = g_qkv16 + (size_t)b * 384 * NPIX;
    const bool evenrow = ((row & 1) == 0);
    #pragma unroll
    for (int mt = 0; mt < 4; mt++) {
        #pragma unroll
        for (int nt = 0; nt < 4; nt++) {
            const int o = m0 + wm0 + mt * 16 + row;
            const int n = n0 + wn0 + nt * 8 + 2 * colk;
            float p0 = __shfl_down_sync(0xFFFFFFFFu, acc[mt][nt][0], 4);
            float p1 = __shfl_down_sync(0xFFFFFFFFu, acc[mt][nt][1], 4);
            float p2 = __shfl_down_sync(0xFFFFFFFFu, acc[mt][nt][2], 4);
            float p3 = __shfl_down_sync(0xFFFFFFFFu, acc[mt][nt][3], 4);
            if (evenrow) {
                uint2 w0 = make_uint2(packh2(acc[mt][nt][0], p0),
                                      packh2(acc[mt][nt][1], p1));
                *(uint2*)(outb + (size_t)(o >> 1) * NPIX + n) = w0;
                uint2 w1 = make_uint2(packh2(acc[mt][nt][2], p2),
                                      packh2(acc[mt][nt][3], p3));
                *(uint2*)(outb + (size_t)((o >> 1) + 4) * NPIX + n) = w1;
            }
        }
    }
}

// ---------------------------------------------------------------------------
// Kernel B: dilated local attention on packed fp16 qkv.
// 2 pixels/thread; hd halves across lane pairs (xor 16); fp32 math.
// word (c2, n) = half2(ch 2c2, ch 2c2+1) at pixel n.
// ---------------------------------------------------------------------------
__global__ __launch_bounds__(256) void attn_kernel()
{
    const int tid  = threadIdx.x;
    const int wid  = tid >> 5, lane = tid & 31;
    const int half = lane >> 4;
    const int pp   = blockIdx.x * 128 + wid * 16 + (lane & 15);
    const int n    = pp * 2;
    const int dh   = blockIdx.y;
    const int dil  = dh >> 2;
    const int head = dh & 3;
    const int b    = blockIdx.z;
    const int d    = dil ? 3 : 2;

    const int r = n / 80;
    const int c = n % 80;

    // q plane c2 rows [0,128), k [128,256), v [256,384)
    const uint32_t* qb = g_qkv16
        + ((size_t)(b * 384 + dil * 64 + head * 16 + half * 8)) * NPIX + n;
    const uint32_t* kb = qb + (size_t)128 * NPIX;
    const uint32_t* vb = qb + (size_t)256 * NPIX;

    // q: 8 words x 2 pixels
    float2 qx[8], qy[8];                 // [j]: channels (2j,2j+1); x=pix n, y=pix n+1
    #pragma unroll
    for (int j = 0; j < 8; j++) {
        uint2 w = *(const uint2*)(qb + j * NPIX);
        qx[j] = unpackh2(w.x);
        qy[j] = unpackh2(w.y);
    }

    float scx[9], scy[9];
    #pragma unroll
    for (int jj = 0; jj < 9; jj++) {
        const int di = jj / 3 - 1, dj = jj % 3 - 1;
        const int rr = r + di * d;
        const int cc0 = c + dj * d, cc1 = cc0 + 1;
        const bool v0 = (cc0 >= 0 && cc0 < 80);
        const bool v1 = (cc1 >= 0 && cc1 < 80);
        float sx = 0.f, sy = 0.f;
        if (rr >= 0 && rr < 80 && (v0 || v1)) {
            const int off = di * d * 80 + dj * d;
            const uint32_t* kp = kb + off;
            if ((off & 1) == 0) {
                #pragma unroll
                for (int j = 0; j < 8; j++) {
                    uint2 w = *(const uint2*)(kp + j * NPIX);
                    float2 k0 = unpackh2(w.x), k1 = unpackh2(w.y);
                    sx = fmaf(qx[j].x, k0.x, sx); sx = fmaf(qx[j].y, k0.y, sx);
                    sy = fmaf(qy[j].x, k1.x, sy); sy = fmaf(qy[j].y, k1.y, sy);
                }
            } else {
                #pragma unroll
                for (int j = 0; j < 8; j++) {
                    float2 k0 = unpackh2(kp[j * NPIX]);
                    float2 k1 = unpackh2(kp[j * NPIX + 1]);
                    sx = fmaf(qx[j].x, k0.x, sx); sx = fmaf(qx[j].y, k0.y, sx);
                    sy = fmaf(qy[j].x, k1.x, sy); sy = fmaf(qy[j].y, k1.y, sy);
                }
            }
            if (!v0) sx = 0.f;
            if (!v1) sy = 0.f;
        }
        sx += __shfl_xor_sync(0xFFFFFFFFu, sx, 16);
        sy += __shfl_xor_sync(0xFFFFFFFFu, sy, 16);
        scx[jj] = sx * SCALE;
        scy[jj] = sy * SCALE;
    }

    float mx = scx[0], my = scy[0];
    #pragma unroll
    for (int jj = 1; jj < 9; jj++) { mx = fmaxf(mx, scx[jj]); my = fmaxf(my, scy[jj]); }
    float sumx = 0.f, sumy = 0.f;
    #pragma unroll
    for (int jj = 0; jj < 9; jj++) {
        scx[jj] = __expf(scx[jj] - mx); sumx += scx[jj];
        scy[jj] = __expf(scy[jj] - my); sumy += scy[jj];
    }
    const float invx = 1.f / sumx, invy = 1.f / sumy;

    float2 ox[8], oy[8];
    #pragma unroll
    for (int j = 0; j < 8; j++) { ox[j] = make_float2(0.f, 0.f); oy[j] = make_float2(0.f, 0.f); }

    #pragma unroll
    for (int jj = 0; jj < 9; jj++) {
        const int di = jj / 3 - 1, dj = jj % 3 - 1;
        const int rr = r + di * d;
        const int cc0 = c + dj * d, cc1 = cc0 + 1;
        const bool v0 = (cc0 >= 0 && cc0 < 80);
        const bool v1 = (cc1 >= 0 && cc1 < 80);
        if (rr >= 0 && rr < 80 && (v0 || v1)) {
            const int off = di * d * 80 + dj * d;
            const float px = v0 ? scx[jj] * invx : 0.f;
            const float py = v1 ? scy[jj] * invy : 0.f;
            const uint32_t* vp = vb + off;
            if ((off & 1) == 0) {
                #pragma unroll
                for (int j = 0; j < 8; j++) {
                    uint2 w = *(const uint2*)(vp + j * NPIX);
                    float2 a0 = unpackh2(w.x), a1 = unpackh2(w.y);
                    ox[j].x = fmaf(px, a0.x, ox[j].x); ox[j].y = fmaf(px, a0.y, ox[j].y);
                    oy[j].x = fmaf(py, a1.x, oy[j].x); oy[j].y = fmaf(py, a1.y, oy[j].y);
                }
            } else {
                #pragma unroll
                for (int j = 0; j < 8; j++) {
                    float2 a0 = unpackh2(vp[j * NPIX]);
                    float2 a1 = unpackh2(vp[j * NPIX + 1]);
                    ox[j].x = fmaf(px, a0.x, ox[j].x); ox[j].y = fmaf(px, a0.y, ox[j].y);
                    oy[j].x = fmaf(py, a1.x, oy[j].x); oy[j].y = fmaf(py, a1.y, oy[j].y);
                }
            }
        }
    }

    uint32_t* ob = g_attn16
        + ((size_t)(b * 128 + dil * 64 + head * 16 + half * 8)) * NPIX + n;
    #pragma unroll
    for (int j = 0; j < 8; j++) {
        uint2 w = make_uint2(packh2(ox[j].x, ox[j].y), packh2(oy[j].x, oy[j].y));
        *(uint2*)(ob + (size_t)j * NPIX) = w;
    }
}

// ---------------------------------------------------------------------------
// Kernel C: out[b][n][o] = sum_c w_proj[o][c]*attn[b][c][n] + bias[o] + resid
// ---------------------------------------------------------------------------
__global__ __launch_bounds__(256, 2) void proj_kernel(const float* __restrict__ bias,
                                                      const float* __restrict__ rgb,
                                                      const float* __restrict__ ir,
                                                      float* __restrict__ out)
{
    __shared__ __align__(16) uint32_t buf[2 * STAGE_W];

    const int b  = blockIdx.z;
    const int n0 = blockIdx.x * 128;
    const int m0 = blockIdx.y * 128;
    const int tid = threadIdx.x;
    const int wid = tid >> 5, lane = tid & 31;
    const int wm0 = (wid >> 2) * 64, wn0 = (wid & 3) * 32;
    const int row = lane >> 2, colk = lane & 3;

    const uint32_t* ab = g_attn16 + (size_t)b * 128 * NPIX;
    const uint32_t sbase = smem_u32(buf);

    auto load_tile = [&](int kt, int stage) {
        const int kw0 = kt * 16;
        const uint32_t As = sbase + stage * STAGE_W * 4;
        const uint32_t Bs = As + AS_SZ * 4;
        #pragma unroll
        for (int j = 0; j < 2; j++) {
            int idx = tid + 256 * j;
            int ar = idx >> 2, ac = (idx & 3) * 4;
            cp16(As + (ar * AS_W + ac) * 4, g_wp16 + (size_t)(m0 + ar) * 128 + kw0 + ac);
        }
        #pragma unroll
        for (int j = 0; j < 2; j++) {
            int idx = tid + 256 * j;
            int bk = idx >> 5, bnc = (idx & 31) * 4;
            cp16(Bs + (bk * BS_W + bnc) * 4, ab + (size_t)(kw0 + bk) * NPIX + n0 + bnc);
        }
    };

    float acc[4][4][4];
    #pragma unroll
    for (int mt = 0; mt < 4; mt++)
        #pragma unroll
        for (int nt = 0; nt < 4; nt++)
            #pragma unroll
            for (int i = 0; i < 4; i++) acc[mt][nt][i] = 0.f;

    load_tile(0, 0); CP_COMMIT();
    load_tile(1, 1); CP_COMMIT();

    for (int kt = 0; kt < 8; kt++) {
        CP_WAIT1();
        __syncthreads();
        const uint32_t* As = buf + (kt & 1) * STAGE_W;
        const uint32_t* Bs = As + AS_SZ;
        gemm_ktile16(As, Bs, wm0, wn0, row, colk, acc);
        __syncthreads();
        if (kt + 2 < 8) load_tile(kt + 2, kt & 1);
        CP_COMMIT();
    }

    const float* resb = ((m0 == 0) ? rgb : ir) + (size_t)b * 128 * NPIX;
    float* outb = out + (size_t)b * NPIX * 256;

    #pragma unroll
    for (int mt = 0; mt < 4; mt++) {
        const int o_lo = m0 + wm0 + mt * 16 + row;
        const int o_hi = o_lo + 8;
        const float bias_lo = __ldg(bias + o_lo);
        const float bias_hi = __ldg(bias + o_hi);
        const float* res_lo = resb + (size_t)(o_lo & 127) * NPIX;
        const float* res_hi = resb + (size_t)(o_hi & 127) * NPIX;
        #pragma unroll
        for (int nt = 0; nt < 4; nt++) {
            const int n = n0 + wn0 + nt * 8 + 2 * colk;
            outb[(size_t)n * 256 + o_lo]       = acc[mt][nt][0] + bias_lo + res_lo[n];
            outb[(size_t)(n + 1) * 256 + o_lo] = acc[mt][nt][1] + bias_lo + res_lo[n + 1];
            outb[(size_t)n * 256 + o_hi]       = acc[mt][nt][2] + bias_hi + res_hi[n];
            outb[(size_t)(n + 1) * 256 + o_hi] = acc[mt][nt][3] + bias_hi + res_hi[n + 1];
        }
    }
}

// ---------------------------------------------------------------------------
extern "C" void kernel_launch(void* const* d_in, const int* in_sizes, int n_in,
                              void* d_out, int out_size)
{
    const float* rgb    = (const float*)d_in[0];
    const float* ir     = (const float*)d_in[1];
    const float* w_qkv  = (const float*)d_in[2];
    const float* w_proj = (const float*)d_in[3];
    const float* b_proj = (const float*)d_in[4];
    float* out = (float*)d_out;

    conv_w<<<1024, 128>>>(w_qkv, w_proj);
    conv_y16<<<dim3(25, 128, 4), 256>>>(rgb, ir);
    qkv_gemm<<<dim3(50, 6, 4), 256>>>();
    attn_kernel<<<dim3(25, 8, 4), 256>>>();
    proj_kernel<<<dim3(50, 2, 4), 256>>>(b_proj, rgb, ir, out);
}

// round 12
// speedup vs baseline: 2.4237x; 1.0448x over previous
#include <cuda_runtime.h>
#include <cstdint>
#include <cuda_fp16.h>

#define NPIX   6400
#define SCALE  0.17677669529663687f   // 32^-0.5

// Scratch (device globals), all fp16 channel-pair packed: word (c2, n) =
// half2(ch 2*c2, ch 2*c2+1) at pixel n. +16 words padding for vector overread.
__device__ __align__(16) uint32_t g_qkv16 [4 * 384 * 6400 + 16]; // q|k|v planes
__device__ __align__(16) uint32_t g_attn16[4 * 128 * 6400 + 16];
__device__ __align__(16) uint32_t g_y16   [4 * 128 * 6400];
__device__ uint32_t g_wq16[768 * 128];   // packed fp16, k-interleaved
__device__ uint32_t g_wp16[256 * 128];

// ---------------------------------------------------------------------------
// Helpers (sm_80-class PTX only: family-safe on compute_103)
// ---------------------------------------------------------------------------
__device__ __forceinline__ uint32_t smem_u32(const void* p) {
    uint32_t a;
    asm("{ .reg .u64 t; cvta.to.shared.u64 t, %1; cvt.u32.u64 %0, t; }" : "=r"(a) : "l"(p));
    return a;
}
__device__ __forceinline__ void cp16(uint32_t dst, const void* src) {
    asm volatile("cp.async.cg.shared.global [%0], [%1], 16;" :: "r"(dst), "l"(src));
}
#define CP_COMMIT() asm volatile("cp.async.commit_group;" ::: "memory")
#define CP_WAIT2()  asm volatile("cp.async.wait_group 2;" ::: "memory")

__device__ __forceinline__ uint32_t packh2(float a, float b) {
    __half2 h = __floats2half2_rn(a, b);          // a -> low half
    return *reinterpret_cast<uint32_t*>(&h);
}
__device__ __forceinline__ float2 unpackh2(uint32_t w) {
    return __half22float2(*reinterpret_cast<__half2*>(&w));
}
__device__ __forceinline__ void mma_f16(float c[4],
                                        uint32_t a0, uint32_t a1, uint32_t a2, uint32_t a3,
                                        uint32_t b0, uint32_t b1) {
    asm volatile("mma.sync.aligned.m16n8k16.row.col.f32.f16.f16.f32 "
                 "{%0,%1,%2,%3}, {%4,%5,%6,%7}, {%8,%9}, {%0,%1,%2,%3};"
                 : "+f"(c[0]), "+f"(c[1]), "+f"(c[2]), "+f"(c[3])
                 : "r"(a0), "r"(a1), "r"(a2), "r"(a3), "r"(b0), "r"(b1));
}

// Smem (per stage, uint32 words): A [128 o][24] (16 words + pad), B [16][136]
#define AS_W    24
#define AS_SZ   (128 * AS_W)
#define BS_W    136
#define BS_SZ   (16 * BS_W)
#define STAGE_W (AS_SZ + BS_SZ)          // 5248 words = 20992 B
#define SMEM_BYTES (3 * STAGE_W * 4)     // 62976 B (3 stages)

// ---------------------------------------------------------------------------
// Prologue 1: weights -> packed fp16 words, 8-group interleaved.
// ---------------------------------------------------------------------------
__global__ __launch_bounds__(128) void conv_w(const float* __restrict__ wq,
                                              const float* __restrict__ wp)
{
    const int row = blockIdx.x;          // 0..1023 : 0..767 wq, 768..1023 wp
    const int j   = threadIdx.x;
    const int jp  = (j & ~7) | (((j & 3) << 1) | ((j >> 2) & 1));
    if (row < 768) {
        g_wq16[row * 128 + jp] = packh2(wq[row * 256 + 2 * j], wq[row * 256 + 2 * j + 1]);
    } else {
        int r = row - 768;
        g_wp16[r * 128 + jp] = packh2(wp[r * 256 + 2 * j], wp[r * 256 + 2 * j + 1]);
    }
}

// ---------------------------------------------------------------------------
// Prologue 2: y = concat(rgb, ir) -> packed fp16 words [b][c2][n]
// ---------------------------------------------------------------------------
__global__ __launch_bounds__(256) void conv_y16(const float* __restrict__ rgb,
                                                const float* __restrict__ ir)
{
    const int n  = blockIdx.x * 256 + threadIdx.x;
    const int c2 = blockIdx.y;
    const int b  = blockIdx.z;
    const float* src = (c2 < 64)
        ? rgb + ((size_t)b * 128 + 2 * c2) * NPIX
        : ir  + ((size_t)b * 128 + 2 * (c2 - 64)) * NPIX;
    g_y16[((size_t)b * 128 + c2) * NPIX + n] = packh2(src[n], src[NPIX + n]);
}

// ---------------------------------------------------------------------------
// GEMM k-tile (32 k = 16 words): warp grid 2(m) x 4(n), warp tile 64 x 32.
// ---------------------------------------------------------------------------
__device__ __forceinline__ void gemm_ktile16(const uint32_t* As, const uint32_t* Bs,
                                             int wm0, int wn0, int row, int colk,
                                             float acc[4][4][4]) {
    #pragma unroll
    for (int ks = 0; ks < 2; ks++) {
        const int kb = ks * 8;
        uint32_t a[4][4], bfr[4][2];
        #pragma unroll
        for (int mt = 0; mt < 4; mt++) {
            const uint32_t* ab = As + (wm0 + mt * 16 + row) * AS_W + kb + 2 * colk;
            uint2 lo = *(const uint2*)ab;
            uint2 hi = *(const uint2*)(ab + 8 * AS_W);
            a[mt][0] = lo.x; a[mt][1] = hi.x; a[mt][2] = lo.y; a[mt][3] = hi.y;
        }
        #pragma unroll
        for (int nt = 0; nt < 4; nt++) {
            const uint32_t* bb = Bs + (kb + colk) * BS_W + wn0 + nt * 8 + row;
            bfr[nt][0] = bb[0];
            bfr[nt][1] = bb[4 * BS_W];
        }
        #pragma unroll
        for (int mt = 0; mt < 4; mt++)
            #pragma unroll
            for (int nt = 0; nt < 4; nt++)
                mma_f16(acc[mt][nt], a[mt][0], a[mt][1], a[mt][2], a[mt][3],
                        bfr[nt][0], bfr[nt][1]);
    }
}

// ---------------------------------------------------------------------------
// Kernel A: qkv (fp16 MMA), 3-stage cp.async pipeline, packed fp16 output.
// ---------------------------------------------------------------------------
__global__ __launch_bounds__(256, 2) void qkv_gemm()
{
    extern __shared__ __align__(16) uint32_t buf[];

    const int b  = blockIdx.z;
    const int n0 = blockIdx.x * 128;
    const int m0 = blockIdx.y * 128;
    const int tid = threadIdx.x;
    const int wid = tid >> 5, lane = tid & 31;
    const int wm0 = (wid >> 2) * 64, wn0 = (wid & 3) * 32;
    const int row = lane >> 2, colk = lane & 3;

    const uint32_t* yb = g_y16 + (size_t)b * 128 * NPIX;
    const uint32_t sbase = smem_u32(buf);

    auto load_tile = [&](int kt, int stage) {
        const int kw0 = kt * 16;
        const uint32_t As = sbase + stage * STAGE_W * 4;
        const uint32_t Bs = As + AS_SZ * 4;
        #pragma unroll
        for (int j = 0; j < 2; j++) {
            int idx = tid + 256 * j;
            int ar = idx >> 2, ac = (idx & 3) * 4;
            cp16(As + (ar * AS_W + ac) * 4, g_wq16 + (size_t)(m0 + ar) * 128 + kw0 + ac);
        }
        #pragma unroll
        for (int j = 0; j < 2; j++) {
            int idx = tid + 256 * j;
            int bk = idx >> 5, bnc = (idx & 31) * 4;
            cp16(Bs + (bk * BS_W + bnc) * 4, yb + (size_t)(kw0 + bk) * NPIX + n0 + bnc);
        }
    };

    float acc[4][4][4];
    #pragma unroll
    for (int mt = 0; mt < 4; mt++)
        #pragma unroll
        for (int nt = 0; nt < 4; nt++)
            #pragma unroll
            for (int i = 0; i < 4; i++) acc[mt][nt][i] = 0.f;

    load_tile(0, 0); CP_COMMIT();
    load_tile(1, 1); CP_COMMIT();
    load_tile(2, 2); CP_COMMIT();

    #pragma unroll
    for (int kt = 0; kt < 8; kt++) {
        CP_WAIT2();
        __syncthreads();
        const int st = kt % 3;
        const uint32_t* As = buf + st * STAGE_W;
        const uint32_t* Bs = As + AS_SZ;
        gemm_ktile16(As, Bs, wm0, wn0, row, colk, acc);
        __syncthreads();
        if (kt + 3 < 8) load_tile(kt + 3, st);
        CP_COMMIT();
    }

    // Epilogue: pair adjacent o rows via shfl, write packed fp16 [b][c2][n].
    uint32_t* outb = g_qkv16 + (size_t)b * 384 * NPIX;
    const bool evenrow = ((row & 1) == 0);
    #pragma unroll
    for (int mt = 0; mt < 4; mt++) {
        #pragma unroll
        for (int nt = 0; nt < 4; nt++) {
            const int o = m0 + wm0 + mt * 16 + row;
            const int n = n0 + wn0 + nt * 8 + 2 * colk;
            float p0 = __shfl_down_sync(0xFFFFFFFFu, acc[mt][nt][0], 4);
            float p1 = __shfl_down_sync(0xFFFFFFFFu, acc[mt][nt][1], 4);
            float p2 = __shfl_down_sync(0xFFFFFFFFu, acc[mt][nt][2], 4);
            float p3 = __shfl_down_sync(0xFFFFFFFFu, acc[mt][nt][3], 4);
            if (evenrow) {
                uint2 w0 = make_uint2(packh2(acc[mt][nt][0], p0),
                                      packh2(acc[mt][nt][1], p1));
                *(uint2*)(outb + (size_t)(o >> 1) * NPIX + n) = w0;
                uint2 w1 = make_uint2(packh2(acc[mt][nt][2], p2),
                                      packh2(acc[mt][nt][3], p3));
                *(uint2*)(outb + (size_t)((o >> 1) + 4) * NPIX + n) = w1;
            }
        }
    }
}

// ---------------------------------------------------------------------------
// Kernel B: dilated local attention on packed fp16 qkv.
// 128-thread blocks, 5 CTAs/SM. 2 pixels/thread; hd halves across lane pairs.
// ---------------------------------------------------------------------------
__global__ __launch_bounds__(128, 5) void attn_kernel()
{
    const int tid  = threadIdx.x;
    const int wid  = tid >> 5, lane = tid & 31;
    const int half = lane >> 4;
    const int pp   = blockIdx.x * 64 + wid * 16 + (lane & 15);
    const int n    = pp * 2;
    const int dh   = blockIdx.y;
    const int dil  = dh >> 2;
    const int head = dh & 3;
    const int b    = blockIdx.z;
    const int d    = dil ? 3 : 2;

    const int r = n / 80;
    const int c = n % 80;

    const uint32_t* qb = g_qkv16
        + ((size_t)(b * 384 + dil * 64 + head * 16 + half * 8)) * NPIX + n;
    const uint32_t* kb = qb + (size_t)128 * NPIX;
    const uint32_t* vb = qb + (size_t)256 * NPIX;

    float2 qx[8], qy[8];
    #pragma unroll
    for (int j = 0; j < 8; j++) {
        uint2 w = *(const uint2*)(qb + j * NPIX);
        qx[j] = unpackh2(w.x);
        qy[j] = unpackh2(w.y);
    }

    float scx[9], scy[9];
    #pragma unroll
    for (int jj = 0; jj < 9; jj++) {
        const int di = jj / 3 - 1, dj = jj % 3 - 1;
        const int rr = r + di * d;
        const int cc0 = c + dj * d, cc1 = cc0 + 1;
        const bool v0 = (cc0 >= 0 && cc0 < 80);
        const bool v1 = (cc1 >= 0 && cc1 < 80);
        float sx = 0.f, sy = 0.f;
        if (rr >= 0 && rr < 80 && (v0 || v1)) {
            const int off = di * d * 80 + dj * d;
            const uint32_t* kp = kb + off;
            if ((off & 1) == 0) {
                #pragma unroll
                for (int j = 0; j < 8; j++) {
                    uint2 w = *(const uint2*)(kp + j * NPIX);
                    float2 k0 = unpackh2(w.x), k1 = unpackh2(w.y);
                    sx = fmaf(qx[j].x, k0.x, sx); sx = fmaf(qx[j].y, k0.y, sx);
                    sy = fmaf(qy[j].x, k1.x, sy); sy = fmaf(qy[j].y, k1.y, sy);
                }
            } else {
                #pragma unroll
                for (int j = 0; j < 8; j++) {
                    float2 k0 = unpackh2(kp[j * NPIX]);
                    float2 k1 = unpackh2(kp[j * NPIX + 1]);
                    sx = fmaf(qx[j].x, k0.x, sx); sx = fmaf(qx[j].y, k0.y, sx);
                    sy = fmaf(qy[j].x, k1.x, sy); sy = fmaf(qy[j].y, k1.y, sy);
                }
            }
            if (!v0) sx = 0.f;
            if (!v1) sy = 0.f;
        }
        sx += __shfl_xor_sync(0xFFFFFFFFu, sx, 16);
        sy += __shfl_xor_sync(0xFFFFFFFFu, sy, 16);
        scx[jj] = sx * SCALE;
        scy[jj] = sy * SCALE;
    }

    float mx = scx[0], my = scy[0];
    #pragma unroll
    for (int jj = 1; jj < 9; jj++) { mx = fmaxf(mx, scx[jj]); my = fmaxf(my, scy[jj]); }
    float sumx = 0.f, sumy = 0.f;
    #pragma unroll
    for (int jj = 0; jj < 9; jj++) {
        scx[jj] = __expf(scx[jj] - mx); sumx += scx[jj];
        scy[jj] = __expf(scy[jj] - my); sumy += scy[jj];
    }
    const float invx = 1.f / sumx, invy = 1.f / sumy;

    float2 ox[8], oy[8];
    #pragma unroll
    for (int j = 0; j < 8; j++) { ox[j] = make_float2(0.f, 0.f); oy[j] = make_float2(0.f, 0.f); }

    #pragma unroll
    for (int jj = 0; jj < 9; jj++) {
        const int di = jj / 3 - 1, dj = jj % 3 - 1;
        const int rr = r + di * d;
        const int cc0 = c + dj * d, cc1 = cc0 + 1;
        const bool v0 = (cc0 >= 0 && cc0 < 80);
        const bool v1 = (cc1 >= 0 && cc1 < 80);
        if (rr >= 0 && rr < 80 && (v0 || v1)) {
            const int off = di * d * 80 + dj * d;
            const float px = v0 ? scx[jj] * invx : 0.f;
            const float py = v1 ? scy[jj] * invy : 0.f;
            const uint32_t* vp = vb + off;
            if ((off & 1) == 0) {
                #pragma unroll
                for (int j = 0; j < 8; j++) {
                    uint2 w = *(const uint2*)(vp + j * NPIX);
                    float2 a0 = unpackh2(w.x), a1 = unpackh2(w.y);
                    ox[j].x = fmaf(px, a0.x, ox[j].x); ox[j].y = fmaf(px, a0.y, ox[j].y);
                    oy[j].x = fmaf(py, a1.x, oy[j].x); oy[j].y = fmaf(py, a1.y, oy[j].y);
                }
            } else {
                #pragma unroll
                for (int j = 0; j < 8; j++) {
                    float2 a0 = unpackh2(vp[j * NPIX]);
                    float2 a1 = unpackh2(vp[j * NPIX + 1]);
                    ox[j].x = fmaf(px, a0.x, ox[j].x); ox[j].y = fmaf(px, a0.y, ox[j].y);
                    oy[j].x = fmaf(py, a1.x, oy[j].x); oy[j].y = fmaf(py, a1.y, oy[j].y);
                }
            }
        }
    }

    uint32_t* ob = g_attn16
        + ((size_t)(b * 128 + dil * 64 + head * 16 + half * 8)) * NPIX + n;
    #pragma unroll
    for (int j = 0; j < 8; j++) {
        uint2 w = make_uint2(packh2(ox[j].x, ox[j].y), packh2(oy[j].x, oy[j].y));
        *(uint2*)(ob + (size_t)j * NPIX) = w;
    }
}

// ---------------------------------------------------------------------------
// Kernel C: proj (fp16 MMA), 3-stage pipeline, + bias + residual epilogue.
// ---------------------------------------------------------------------------
__global__ __launch_bounds__(256, 2) void proj_kernel(const float* __restrict__ bias,
                                                      const float* __restrict__ rgb,
                                                      const float* __restrict__ ir,
                                                      float* __restrict__ out)
{
    extern __shared__ __align__(16) uint32_t buf[];

    const int b  = blockIdx.z;
    const int n0 = blockIdx.x * 128;
    const int m0 = blockIdx.y * 128;
    const int tid = threadIdx.x;
    const int wid = tid >> 5, lane = tid & 31;
    const int wm0 = (wid >> 2) * 64, wn0 = (wid & 3) * 32;
    const int row = lane >> 2, colk = lane & 3;

    const uint32_t* ab = g_attn16 + (size_t)b * 128 * NPIX;
    const uint32_t sbase = smem_u32(buf);

    auto load_tile = [&](int kt, int stage) {
        const int kw0 = kt * 16;
        const uint32_t As = sbase + stage * STAGE_W * 4;
        const uint32_t Bs = As + AS_SZ * 4;
        #pragma unroll
        for (int j = 0; j < 2; j++) {
            int idx = tid + 256 * j;
            int ar = idx >> 2, ac = (idx & 3) * 4;
            cp16(As + (ar * AS_W + ac) * 4, g_wp16 + (size_t)(m0 + ar) * 128 + kw0 + ac);
        }
        #pragma unroll
        for (int j = 0; j < 2; j++) {
            int idx = tid + 256 * j;
            int bk = idx >> 5, bnc = (idx & 31) * 4;
            cp16(Bs + (bk * BS_W + bnc) * 4, ab + (size_t)(kw0 + bk) * NPIX + n0 + bnc);
        }
    };

    float acc[4][4][4];
    #pragma unroll
    for (int mt = 0; mt < 4; mt++)
        #pragma unroll
        for (int nt = 0; nt < 4; nt++)
            #pragma unroll
            for (int i = 0; i < 4; i++) acc[mt][nt][i] = 0.f;

    load_tile(0, 0); CP_COMMIT();
    load_tile(1, 1); CP_COMMIT();
    load_tile(2, 2); CP_COMMIT();

    #pragma unroll
    for (int kt = 0; kt < 8; kt++) {
        CP_WAIT2();
        __syncthreads();
        const int st = kt % 3;
        const uint32_t* As = buf + st * STAGE_W;
        const uint32_t* Bs = As + AS_SZ;
        gemm_ktile16(As, Bs, wm0, wn0, row, colk, acc);
        __syncthreads();
        if (kt + 3 < 8) load_tile(kt + 3, st);
        CP_COMMIT();
    }

    const float* resb = ((m0 == 0) ? rgb : ir) + (size_t)b * 128 * NPIX;
    float* outb = out + (size_t)b * NPIX * 256;

    #pragma unroll
    for (int mt = 0; mt < 4; mt++) {
        const int o_lo = m0 + wm0 + mt * 16 + row;
        const int o_hi = o_lo + 8;
        const float bias_lo = __ldg(bias + o_lo);
        const float bias_hi = __ldg(bias + o_hi);
        const float* res_lo = resb + (size_t)(o_lo & 127) * NPIX;
        const float* res_hi = resb + (size_t)(o_hi & 127) * NPIX;
        #pragma unroll
        for (int nt = 0; nt < 4; nt++) {
            const int n = n0 + wn0 + nt * 8 + 2 * colk;
            outb[(size_t)n * 256 + o_lo]       = acc[mt][nt][0] + bias_lo + res_lo[n];
            outb[(size_t)(n + 1) * 256 + o_lo] = acc[mt][nt][1] + bias_lo + res_lo[n + 1];
            outb[(size_t)n * 256 + o_hi]       = acc[mt][nt][2] + bias_hi + res_hi[n];
            outb[(size_t)(n + 1) * 256 + o_hi] = acc[mt][nt][3] + bias_hi + res_hi[n + 1];
        }
    }
}

// ---------------------------------------------------------------------------
extern "C" void kernel_launch(void* const* d_in, const int* in_sizes, int n_in,
                              void* d_out, int out_size)
{
    const float* rgb    = (const float*)d_in[0];
    const float* ir     = (const float*)d_in[1];
    const float* w_qkv  = (const float*)d_in[2];
    const float* w_proj = (const float*)d_in[3];
    const float* b_proj = (const float*)d_in[4];
    float* out = (float*)d_out;

    cudaFuncSetAttribute(qkv_gemm, cudaFuncAttributeMaxDynamicSharedMemorySize, SMEM_BYTES);
    cudaFuncSetAttribute(proj_kernel, cudaFuncAttributeMaxDynamicSharedMemorySize, SMEM_BYTES);

    conv_w<<<1024, 128>>>(w_qkv, w_proj);
    conv_y16<<<dim3(25, 128, 4), 256>>>(rgb, ir);
    qkv_gemm<<<dim3(50, 6, 4), 256, SMEM_BYTES>>>();
    attn_kernel<<<dim3(50, 8, 4), 128>>>();
    proj_kernel<<<dim3(50, 2, 4), 256, SMEM_BYTES>>>(b_proj, rgb, ir, out);
}